// round 6
// baseline (speedup 1.0000x reference)
#include <cuda_runtime.h>
#include <cuda_fp16.h>
#include <math.h>
#include <stdint.h>

// ---------------- problem constants ----------------
#define BQ    16
#define ISZ   56
#define DIM   768
#define NHD   12
#define HDIM  64
#define WSZ   14
#define TOK   196
#define NWIN  256
#define MROWS 50176
#define MLPD  3072

typedef unsigned long long ull;
typedef __half fp16;

// ---------------- scratch (device globals) ----------------
__device__ __align__(16) fp16  g_a1h[(size_t)MROWS * DIM],  g_a1l[(size_t)MROWS * DIM];
__device__ __align__(16) float g_qkv[(size_t)MROWS * 3 * DIM];
__device__ __align__(16) fp16  g_ath[(size_t)MROWS * DIM],  g_atl[(size_t)MROWS * DIM];
__device__ __align__(16) float g_hid[(size_t)MROWS * DIM];
__device__ __align__(16) fp16  g_a2h[(size_t)MROWS * DIM],  g_a2l[(size_t)MROWS * DIM];
__device__ __align__(16) fp16  g_hh [(size_t)MROWS * MLPD], g_hl [(size_t)MROWS * MLPD];
// transposed fp16 weights: T[n][k]
__device__ __align__(16) fp16  g_wq[(size_t)(3 * DIM) * DIM];
__device__ __align__(16) fp16  g_wp[(size_t)DIM * DIM];
__device__ __align__(16) fp16  g_w1[(size_t)MLPD * DIM];
__device__ __align__(16) fp16  g_w2[(size_t)DIM * MLPD];

// ---------------- small helpers ----------------
__device__ __forceinline__ uint32_t split_pack_h(float x0, float x1, uint32_t& lopack) {
    fp16 h0 = __float2half_rn(x0), h1 = __float2half_rn(x1);
    fp16 l0 = __float2half_rn(x0 - __half2float(h0));
    fp16 l1 = __float2half_rn(x1 - __half2float(h1));
    uint16_t uh0 = *(uint16_t*)&h0, uh1 = *(uint16_t*)&h1;
    uint16_t ul0 = *(uint16_t*)&l0, ul1 = *(uint16_t*)&l1;
    lopack = (uint32_t)ul0 | ((uint32_t)ul1 << 16);
    return (uint32_t)uh0 | ((uint32_t)uh1 << 16);
}
__device__ __forceinline__ uint32_t smem_u32(const void* p) {
    uint32_t a;
    asm("{ .reg .u64 t; cvta.to.shared.u64 t, %1; cvt.u32.u64 %0, t; }" : "=r"(a) : "l"(p));
    return a;
}

// f32x2 packed math (attention)
__device__ __forceinline__ ull pk2(float lo, float hi) {
    ull r; asm("mov.b64 %0, {%1, %2};" : "=l"(r) : "f"(lo), "f"(hi)); return r;
}
__device__ __forceinline__ float2 upk2(ull v) {
    float2 f; asm("mov.b64 {%0, %1}, %2;" : "=f"(f.x), "=f"(f.y) : "l"(v)); return f;
}
__device__ __forceinline__ void fma2(ull& c, ull a, ull b) {
    asm("fma.rn.f32x2 %0, %1, %2, %3;" : "=l"(c) : "l"(a), "l"(b), "l"(c));
}
__device__ __forceinline__ void mul2(ull& c, ull a, ull b) {
    asm("mul.rn.f32x2 %0, %1, %2;" : "=l"(c) : "l"(a), "l"(b));
}

// window-token row m -> flat pixel p
__device__ __forceinline__ int m_to_p(int m) {
    int win = m / TOK, tok = m - win * TOK;
    int b = win >> 4, wr = win & 15;
    int wh = wr >> 2, ww = wr & 3;
    int i = tok / WSZ, j = tok - i * WSZ;
    return (b * ISZ + wh * WSZ + i) * ISZ + ww * WSZ + j;
}

// ---------------- mma / ldmatrix / cp.async helpers (base sm_80+ PTX) ------
__device__ __forceinline__ void mma16816h(float* d, const uint32_t* a, const uint32_t* b) {
    asm volatile("mma.sync.aligned.m16n8k16.row.col.f32.f16.f16.f32 "
        "{%0,%1,%2,%3},{%4,%5,%6,%7},{%8,%9},{%0,%1,%2,%3};"
        : "+f"(d[0]), "+f"(d[1]), "+f"(d[2]), "+f"(d[3])
        : "r"(a[0]), "r"(a[1]), "r"(a[2]), "r"(a[3]), "r"(b[0]), "r"(b[1]));
}
__device__ __forceinline__ void ldx4(uint32_t* r, uint32_t addr) {
    asm volatile("ldmatrix.sync.aligned.m8n8.x4.shared.b16 {%0,%1,%2,%3}, [%4];"
        : "=r"(r[0]), "=r"(r[1]), "=r"(r[2]), "=r"(r[3]) : "r"(addr));
}
__device__ __forceinline__ void cpa16(uint32_t dst, const void* src) {
    asm volatile("cp.async.cg.shared.global [%0], [%1], 16;" :: "r"(dst), "l"(src));
}
#define CP_COMMIT() asm volatile("cp.async.commit_group;" ::: "memory")
#define CP_WAIT1()  asm volatile("cp.async.wait_group 1;" ::: "memory")

// ---------------- weight transpose -> fp16 ----------------
__global__ void __launch_bounds__(256) wprep_k(const float* __restrict__ W,
                                               fp16* __restrict__ Th,
                                               int K, int N) {
    __shared__ float t[32][33];
    int nb = blockIdx.x * 32, kb = blockIdx.y * 32;
    int tx = threadIdx.x, ty = threadIdx.y;
#pragma unroll
    for (int j = 0; j < 32; j += 8)
        t[ty + j][tx] = W[(size_t)(kb + ty + j) * N + nb + tx];
    __syncthreads();
#pragma unroll
    for (int j = 0; j < 32; j += 8)
        Th[(size_t)(nb + ty + j) * K + kb + tx] = __float2half_rn(t[tx][ty + j]);
}

// ---------------- LayerNorm -> hi/lo fp16 planes ----------------
__global__ void __launch_bounds__(256) ln_k(const float* __restrict__ in,
                                            const float* __restrict__ gg,
                                            const float* __restrict__ bb,
                                            fp16* __restrict__ oh, fp16* __restrict__ ol,
                                            int windowed) {
    int blk = blockIdx.x;
    int src = windowed ? m_to_p(blk) : blk;
    const float* xr = in + (size_t)src * DIM;
    int t = threadIdx.x;
    float v0 = xr[t], v1 = xr[t + 256], v2 = xr[t + 512];
    float s = v0 + v1 + v2;
    float sq = v0 * v0 + v1 * v1 + v2 * v2;
#pragma unroll
    for (int o = 16; o > 0; o >>= 1) {
        s  += __shfl_xor_sync(0xffffffffu, s, o);
        sq += __shfl_xor_sync(0xffffffffu, sq, o);
    }
    __shared__ float sh[16];
    int wid = t >> 5, lane = t & 31;
    if (!lane) { sh[wid] = s; sh[8 + wid] = sq; }
    __syncthreads();
    float st = 0.f, sqt = 0.f;
#pragma unroll
    for (int i = 0; i < 8; i++) { st += sh[i]; sqt += sh[8 + i]; }
    float mu = st * (1.0f / 768.0f);
    float var = sqt * (1.0f / 768.0f) - mu * mu;
    float rstd = rsqrtf(var + 1e-5f);
    size_t base = (size_t)blk * DIM;
#pragma unroll
    for (int c = 0; c < 3; c++) {
        int idx = t + c * 256;
        float v = (c == 0 ? v0 : (c == 1 ? v1 : v2));
        float y = (v - mu) * rstd * gg[idx] + bb[idx];
        fp16 h = __float2half_rn(y);
        oh[base + idx] = h;
        ol[base + idx] = __float2half_rn(y - __half2float(h));
    }
}

// ---------------- HMMA GEMM: C(MxN) = A(MxK) * B^T, B stored [N][K] --------
// A split into fp16 hi/lo planes (exact to ~2^-23), B single RN fp16 plane.
// 2 MMA passes: Ah*Bh + Al*Bh. CTA 128x128, 8 warps of 32x64, k-chunk 32,
// 2-stage cp.async, 2 CTAs/SM.
// EPI: 0=+bias->f32  1=gelu(+bias)->hi/lo planes  2=+bias+res scatter->f32  3=+bias+res->f32
#define A_PL 10240                          // 128 rows * 80B (64B data + pad)
#define B_PL 10240
#define STAGE_BYTES (2 * A_PL + B_PL)       // 30720
#define SMEM_GEMM (2 * STAGE_BYTES + 1024)  // 62464

template <int EPI>
__global__ void __launch_bounds__(256, 2)
tgemm_k(const fp16* __restrict__ Ah, const fp16* __restrict__ Al,
        const fp16* __restrict__ Bh,
        const float* __restrict__ bias, const float* __restrict__ res,
        float* __restrict__ C, fp16* __restrict__ Ch, fp16* __restrict__ Cl,
        int M, int N, int K) {
    extern __shared__ char dyn[];
    uint32_t sb = (smem_u32(dyn) + 255) & ~255u;

    const int tid = threadIdx.x, lane = tid & 31, wid = tid >> 5;
    const int bm = blockIdx.y * 128, bn = blockIdx.x * 128;
    const int wm = (wid >> 1) * 32, wn = (wid & 1) * 64;
    const int nk = K >> 5;

    // cp.async: 6 x 16B chunks per thread (A hi, A lo, B hi = 1536 chunks total)
    const fp16* gp[6]; uint32_t so[6];
#pragma unroll
    for (int q = 0; q < 6; q++) {
        int i = tid + q * 256;
        if (i < 1024) {
            int pl = i >> 9, idx = i & 511, r = idx >> 2, c = idx & 3;
            gp[q] = (pl ? Al : Ah) + (size_t)(bm + r) * K + c * 8;
            so[q] = (uint32_t)(pl * A_PL + r * 80 + c * 16);
        } else {
            int j = i - 1024, r = j >> 2, c = j & 3;
            gp[q] = Bh + (size_t)(bn + r) * K + c * 8;
            so[q] = (uint32_t)(2 * A_PL + r * 80 + c * 16);
        }
    }

    auto issue = [&](int stage, int t) {
        uint32_t s = sb + stage * STAGE_BYTES;
        int k0 = t * 32;
#pragma unroll
        for (int q = 0; q < 6; q++) cpa16(s + so[q], gp[q] + k0);
    };

    float acc[64];
#pragma unroll
    for (int i = 0; i < 64; i++) acc[i] = 0.f;

    // ldmatrix lane offsets (80B row stride: conflict-free)
    const uint32_t aoff = (uint32_t)(((lane & 7) + ((lane >> 3) & 1) * 8) * 80 + (lane >> 4) * 16);
    const int bj = lane >> 3;
    const uint32_t boff = (uint32_t)((((bj >> 1) * 8) + (lane & 7)) * 80 + (bj & 1) * 16);

    issue(0, 0); CP_COMMIT();
    issue(1, 1); CP_COMMIT();

    for (int t = 0; t < nk; ++t) {
        CP_WAIT1();
        __syncthreads();

        uint32_t s = sb + (t & 1) * STAGE_BYTES;
#pragma unroll
        for (int ks = 0; ks < 2; ks++) {
            uint32_t kb = ks * 32;
            uint32_t ah[2][4], al[2][4];
#pragma unroll
            for (int mi = 0; mi < 2; mi++) {
                uint32_t rowb = (uint32_t)((wm + mi * 16) * 80) + kb;
                ldx4(ah[mi], s + rowb + aoff);
                ldx4(al[mi], s + A_PL + rowb + aoff);
            }
#pragma unroll
            for (int p = 0; p < 4; p++) {
                uint32_t bh[4];
                uint32_t rowb = (uint32_t)((wn + p * 16) * 80) + kb;
                ldx4(bh, s + 2 * A_PL + rowb + boff);
                // pass 1: Ah*Bh (4 independent accumulators)
#pragma unroll
                for (int mi = 0; mi < 2; mi++) {
                    mma16816h(&acc[(mi * 8 + 2 * p) * 4],     ah[mi], bh);
                    mma16816h(&acc[(mi * 8 + 2 * p + 1) * 4], ah[mi], bh + 2);
                }
                // pass 2: Al*Bh
#pragma unroll
                for (int mi = 0; mi < 2; mi++) {
                    mma16816h(&acc[(mi * 8 + 2 * p) * 4],     al[mi], bh);
                    mma16816h(&acc[(mi * 8 + 2 * p + 1) * 4], al[mi], bh + 2);
                }
            }
        }

        __syncthreads();
        if (t + 2 < nk) issue(t & 1, t + 2);
        CP_COMMIT();
    }

    // -------- epilogue --------
#pragma unroll
    for (int mi = 0; mi < 2; mi++) {
        int r0 = bm + wm + mi * 16 + (lane >> 2);
#pragma unroll
        for (int ni = 0; ni < 8; ni++) {
            int gn = bn + wn + ni * 8 + (lane & 3) * 2;
            float* a = &acc[(mi * 8 + ni) * 4];
            float b0 = bias[gn], b1 = bias[gn + 1];
#pragma unroll
            for (int h = 0; h < 2; h++) {
                int row = r0 + h * 8;
                float x0 = a[h * 2] + b0, x1 = a[h * 2 + 1] + b1;
                if (EPI == 1) {
                    float g0 = 0.5f * x0 * (1.0f + erff(x0 * 0.70710678118654752f));
                    float g1 = 0.5f * x1 * (1.0f + erff(x1 * 0.70710678118654752f));
                    uint32_t lo;
                    uint32_t hi = split_pack_h(g0, g1, lo);
                    *(uint32_t*)((char*)Ch + ((size_t)row * N + gn) * 2) = hi;
                    *(uint32_t*)((char*)Cl + ((size_t)row * N + gn) * 2) = lo;
                } else if (EPI == 2) {
                    int p = m_to_p(row);
                    const float* rp = res + (size_t)p * DIM + gn;
                    float2 o; o.x = x0 + rp[0]; o.y = x1 + rp[1];
                    *(float2*)(C + (size_t)p * DIM + gn) = o;
                } else if (EPI == 3) {
                    const float* rp = res + (size_t)row * N + gn;
                    float2 o; o.x = x0 + rp[0]; o.y = x1 + rp[1];
                    *(float2*)(C + (size_t)row * N + gn) = o;
                } else {
                    float2 o; o.x = x0; o.y = x1;
                    *(float2*)(C + (size_t)row * N + gn) = o;
                }
            }
        }
    }
}

// ---------------- window attention (fp32 in, hi/lo fp16 planes out) ----------
#define ATTN_SMEM (2 * TOK * HDIM * 4)

__global__ void __launch_bounds__(224) attn_k(const float* __restrict__ qkv,
                                              const float* __restrict__ rph,
                                              const float* __restrict__ rpw,
                                              fp16* __restrict__ oh,
                                              fp16* __restrict__ ol) {
    extern __shared__ float sm[];
    float* Ks = sm;
    float* Vs = sm + TOK * HDIM;
    const int win = blockIdx.x, head = blockIdx.y;
    const int tid = threadIdx.x;
    const float* base = qkv + (size_t)win * TOK * (3 * DIM) + head * HDIM;

    for (int idx = tid; idx < TOK * 16; idx += 224) {
        int kt = idx >> 4, d4 = (idx & 15) << 2;
        *(float4*)&Ks[kt * HDIM + d4] = *(const float4*)(base + (size_t)kt * (3 * DIM) + DIM + d4);
        *(float4*)&Vs[kt * HDIM + d4] = *(const float4*)(base + (size_t)kt * (3 * DIM) + 2 * DIM + d4);
    }
    __syncthreads();
    if (tid >= TOK) return;

    const int qi = tid / WSZ, qj = tid - qi * WSZ;

    ull q2[32];
#pragma unroll
    for (int d = 0; d < HDIM; d += 4) {
        float4 t = *(const float4*)(base + (size_t)tid * (3 * DIM) + d);
        q2[(d >> 1)]     = pk2(t.x * 0.125f, t.y * 0.125f);
        q2[(d >> 1) + 1] = pk2(t.z * 0.125f, t.w * 0.125f);
    }

    float relh[WSZ], relw[WSZ];
#pragma unroll
    for (int kh = 0; kh < WSZ; kh++) {
        const ull* r1 = (const ull*)(rph + (size_t)(qi - kh + WSZ - 1) * HDIM);
        const ull* r2 = (const ull*)(rpw + (size_t)(qj - kh + WSZ - 1) * HDIM);
        ull a0 = 0, a1 = 0, b0 = 0, b1 = 0;
#pragma unroll
        for (int j = 0; j < 32; j += 2) {
            fma2(a0, q2[j], r1[j]); fma2(a1, q2[j + 1], r1[j + 1]);
            fma2(b0, q2[j], r2[j]); fma2(b1, q2[j + 1], r2[j + 1]);
        }
        float2 fa0 = upk2(a0), fa1 = upk2(a1), fb0 = upk2(b0), fb1 = upk2(b1);
        relh[kh] = 8.0f * (fa0.x + fa0.y + fa1.x + fa1.y);
        relw[kh] = 8.0f * (fb0.x + fb0.y + fb1.x + fb1.y);
    }

    ull acc[32];
#pragma unroll
    for (int j = 0; j < 32; j++) acc[j] = 0ull;
    float mmax = -INFINITY, l = 0.f;

    for (int kh = 0; kh < WSZ; kh++) {
        for (int kw = 0; kw < WSZ; kw++) {
            int kt = kh * WSZ + kw;
            const ull* kp = (const ull*)&Ks[kt * HDIM];
            ull s0 = 0, s1 = 0, s2 = 0, s3 = 0;
#pragma unroll
            for (int j = 0; j < 32; j += 4) {
                fma2(s0, q2[j],     kp[j]);
                fma2(s1, q2[j + 1], kp[j + 1]);
                fma2(s2, q2[j + 2], kp[j + 2]);
                fma2(s3, q2[j + 3], kp[j + 3]);
            }
            float2 f0 = upk2(s0), f1 = upk2(s1), f2 = upk2(s2), f3 = upk2(s3);
            float s = f0.x + f0.y + f1.x + f1.y + f2.x + f2.y + f3.x + f3.y
                    + relh[kh] + relw[kw];
            if (s > mmax) {
                float c = expf(mmax - s);
                l *= c;
                ull c2 = pk2(c, c);
#pragma unroll
                for (int j = 0; j < 32; j++) mul2(acc[j], acc[j], c2);
                mmax = s;
            }
            float p = expf(s - mmax);
            l += p;
            ull p2 = pk2(p, p);
            const ull* vp = (const ull*)&Vs[kt * HDIM];
#pragma unroll
            for (int j = 0; j < 32; j++) fma2(acc[j], p2, vp[j]);
        }
    }

    float inv = 1.0f / l;
    size_t ob = ((size_t)win * TOK + tid) * DIM + head * HDIM;
    uint32_t* ph = (uint32_t*)((char*)oh + ob * 2);
    uint32_t* pl = (uint32_t*)((char*)ol + ob * 2);
#pragma unroll
    for (int j = 0; j < 32; j++) {
        float2 f = upk2(acc[j]);
        uint32_t lo;
        uint32_t hi = split_pack_h(f.x * inv, f.y * inv, lo);
        ph[j] = hi; pl[j] = lo;
    }
}

// ---------------- launcher ----------------
extern "C" void kernel_launch(void* const* d_in, const int* in_sizes, int n_in,
                              void* d_out, int out_size) {
    const float* x     = (const float*)d_in[0];
    const float* n1g   = (const float*)d_in[1];
    const float* n1b   = (const float*)d_in[2];
    const float* qkvw  = (const float*)d_in[3];
    const float* qkvb  = (const float*)d_in[4];
    const float* projw = (const float*)d_in[5];
    const float* projb = (const float*)d_in[6];
    const float* rph   = (const float*)d_in[7];
    const float* rpw   = (const float*)d_in[8];
    const float* n2g   = (const float*)d_in[9];
    const float* n2b   = (const float*)d_in[10];
    const float* l1w   = (const float*)d_in[11];
    const float* l1b   = (const float*)d_in[12];
    const float* l2w   = (const float*)d_in[13];
    const float* l2b   = (const float*)d_in[14];
    float* out = (float*)d_out;

    cudaFuncSetAttribute(attn_k, cudaFuncAttributeMaxDynamicSharedMemorySize, ATTN_SMEM);
    cudaFuncSetAttribute(tgemm_k<0>, cudaFuncAttributeMaxDynamicSharedMemorySize, SMEM_GEMM);
    cudaFuncSetAttribute(tgemm_k<1>, cudaFuncAttributeMaxDynamicSharedMemorySize, SMEM_GEMM);
    cudaFuncSetAttribute(tgemm_k<2>, cudaFuncAttributeMaxDynamicSharedMemorySize, SMEM_GEMM);
    cudaFuncSetAttribute(tgemm_k<3>, cudaFuncAttributeMaxDynamicSharedMemorySize, SMEM_GEMM);

    fp16 *p_a1h, *p_a1l, *p_ath, *p_atl, *p_a2h, *p_a2l, *p_hh, *p_hl;
    fp16 *p_wq, *p_wp, *p_w1, *p_w2;
    float *p_qkv, *p_hid;
    cudaGetSymbolAddress((void**)&p_a1h, g_a1h); cudaGetSymbolAddress((void**)&p_a1l, g_a1l);
    cudaGetSymbolAddress((void**)&p_qkv, g_qkv);
    cudaGetSymbolAddress((void**)&p_ath, g_ath); cudaGetSymbolAddress((void**)&p_atl, g_atl);
    cudaGetSymbolAddress((void**)&p_hid, g_hid);
    cudaGetSymbolAddress((void**)&p_a2h, g_a2h); cudaGetSymbolAddress((void**)&p_a2l, g_a2l);
    cudaGetSymbolAddress((void**)&p_hh,  g_hh);  cudaGetSymbolAddress((void**)&p_hl,  g_hl);
    cudaGetSymbolAddress((void**)&p_wq, g_wq);   cudaGetSymbolAddress((void**)&p_wp, g_wp);
    cudaGetSymbolAddress((void**)&p_w1, g_w1);   cudaGetSymbolAddress((void**)&p_w2, g_w2);

    dim3 tb(32, 8);
    wprep_k<<<dim3(3 * DIM / 32, DIM / 32), tb>>>(qkvw,  p_wq, DIM,  3 * DIM);
    wprep_k<<<dim3(DIM / 32, DIM / 32),     tb>>>(projw, p_wp, DIM,  DIM);

    // 1) LN1 + window-partition -> hi/lo planes
    ln_k<<<MROWS, 256>>>(x, n1g, n1b, p_a1h, p_a1l, 1);

    // 2) QKV GEMM -> fp32 qkv   (50176 x 2304 x 768)
    tgemm_k<0><<<dim3(18, 392), 256, SMEM_GEMM>>>(p_a1h, p_a1l, p_wq,
        qkvb, nullptr, p_qkv, nullptr, nullptr, MROWS, 3 * DIM, DIM);

    // 3) attention -> hi/lo planes
    attn_k<<<dim3(NWIN, NHD), 224, ATTN_SMEM>>>(p_qkv, rph, rpw, p_ath, p_atl);

    // 4) proj GEMM + unpartition + residual -> g_hid (fp32)   (50176 x 768 x 768)
    tgemm_k<2><<<dim3(6, 392), 256, SMEM_GEMM>>>(p_ath, p_atl, p_wp,
        projb, x, p_hid, nullptr, nullptr, MROWS, DIM, DIM);

    // 5) LN2 -> hi/lo planes
    ln_k<<<MROWS, 256>>>(p_hid, n2g, n2b, p_a2h, p_a2l, 0);

    wprep_k<<<dim3(MLPD / 32, DIM / 32), tb>>>(l1w, p_w1, DIM, MLPD);

    // 6) MLP1 + gelu -> hi/lo planes   (50176 x 3072 x 768)
    tgemm_k<1><<<dim3(24, 392), 256, SMEM_GEMM>>>(p_a2h, p_a2l, p_w1,
        l1b, nullptr, nullptr, p_hh, p_hl, MROWS, MLPD, DIM);

    wprep_k<<<dim3(DIM / 32, MLPD / 32), tb>>>(l2w, p_w2, MLPD, DIM);

    // 7) MLP2 + residual -> out (fp32)   (50176 x 768 x 3072)
    tgemm_k<3><<<dim3(6, 392), 256, SMEM_GEMM>>>(p_hh, p_hl, p_w2,
        l2b, p_hid, out, nullptr, nullptr, MROWS, DIM, MLPD);
}

// round 7
// speedup vs baseline: 1.5030x; 1.5030x over previous
#include <cuda_runtime.h>
#include <math.h>
#include <stdint.h>

// ---------------- problem constants ----------------
#define BQ    16
#define ISZ   56
#define DIM   768
#define NHD   12
#define HDIM  64
#define WSZ   14
#define TOK   196
#define NWIN  256
#define MROWS 50176
#define MLPD  3072

typedef unsigned long long ull;

// ---------------- scratch (device globals) ----------------
// single tf32-pre-rounded fp32 planes (same bytes as hi+lo bf16 pairs)
__device__ __align__(16) float g_a1 [(size_t)MROWS * DIM];
__device__ __align__(16) float g_qkv[(size_t)MROWS * 3 * DIM];
__device__ __align__(16) float g_at [(size_t)MROWS * DIM];
__device__ __align__(16) float g_hid[(size_t)MROWS * DIM];
__device__ __align__(16) float g_a2 [(size_t)MROWS * DIM];
__device__ __align__(16) float g_h  [(size_t)MROWS * MLPD];
// transposed tf32-rounded weights: T[n][k]
__device__ __align__(16) float g_wq[(size_t)(3 * DIM) * DIM];
__device__ __align__(16) float g_wp[(size_t)DIM * DIM];
__device__ __align__(16) float g_w1[(size_t)MLPD * DIM];
__device__ __align__(16) float g_w2[(size_t)DIM * MLPD];

// ---------------- helpers ----------------
__device__ __forceinline__ float tf32r(float x) {
    uint32_t u;
    asm("cvt.rna.tf32.f32 %0, %1;" : "=r"(u) : "f"(x));
    return __uint_as_float(u);
}
__device__ __forceinline__ uint32_t smem_u32(const void* p) {
    uint32_t a;
    asm("{ .reg .u64 t; cvta.to.shared.u64 t, %1; cvt.u32.u64 %0, t; }" : "=r"(a) : "l"(p));
    return a;
}

// f32x2 packed math (attention)
__device__ __forceinline__ ull pk2(float lo, float hi) {
    ull r; asm("mov.b64 %0, {%1, %2};" : "=l"(r) : "f"(lo), "f"(hi)); return r;
}
__device__ __forceinline__ float2 upk2(ull v) {
    float2 f; asm("mov.b64 {%0, %1}, %2;" : "=f"(f.x), "=f"(f.y) : "l"(v)); return f;
}
__device__ __forceinline__ void fma2(ull& c, ull a, ull b) {
    asm("fma.rn.f32x2 %0, %1, %2, %3;" : "=l"(c) : "l"(a), "l"(b), "l"(c));
}
__device__ __forceinline__ void mul2(ull& c, ull a, ull b) {
    asm("mul.rn.f32x2 %0, %1, %2;" : "=l"(c) : "l"(a), "l"(b));
}

// window-token row m -> flat pixel p
__device__ __forceinline__ int m_to_p(int m) {
    int win = m / TOK, tok = m - win * TOK;
    int b = win >> 4, wr = win & 15;
    int wh = wr >> 2, ww = wr & 3;
    int i = tok / WSZ, j = tok - i * WSZ;
    return (b * ISZ + wh * WSZ + i) * ISZ + ww * WSZ + j;
}

// ---------------- mma / ldmatrix / cp.async (base sm_80+ PTX) --------------
__device__ __forceinline__ void mma1688t(float* d, const uint32_t* a, const uint32_t* b) {
    asm volatile("mma.sync.aligned.m16n8k8.row.col.f32.tf32.tf32.f32 "
        "{%0,%1,%2,%3},{%4,%5,%6,%7},{%8,%9},{%0,%1,%2,%3};"
        : "+f"(d[0]), "+f"(d[1]), "+f"(d[2]), "+f"(d[3])
        : "r"(a[0]), "r"(a[1]), "r"(a[2]), "r"(a[3]), "r"(b[0]), "r"(b[1]));
}
__device__ __forceinline__ void ldx4(uint32_t* r, uint32_t addr) {
    asm volatile("ldmatrix.sync.aligned.m8n8.x4.shared.b16 {%0,%1,%2,%3}, [%4];"
        : "=r"(r[0]), "=r"(r[1]), "=r"(r[2]), "=r"(r[3]) : "r"(addr));
}
__device__ __forceinline__ void cpa16(uint32_t dst, const void* src) {
    asm volatile("cp.async.cg.shared.global [%0], [%1], 16;" :: "r"(dst), "l"(src));
}
#define CP_COMMIT() asm volatile("cp.async.commit_group;" ::: "memory")
#define CP_WAIT1()  asm volatile("cp.async.wait_group 1;" ::: "memory")

// ---------------- weight transpose -> tf32-rounded fp32 ----------------
__global__ void __launch_bounds__(256) wprep_k(const float* __restrict__ W,
                                               float* __restrict__ T,
                                               int K, int N) {
    __shared__ float t[32][33];
    int nb = blockIdx.x * 32, kb = blockIdx.y * 32;
    int tx = threadIdx.x, ty = threadIdx.y;
#pragma unroll
    for (int j = 0; j < 32; j += 8)
        t[ty + j][tx] = W[(size_t)(kb + ty + j) * N + nb + tx];
    __syncthreads();
#pragma unroll
    for (int j = 0; j < 32; j += 8)
        T[(size_t)(nb + ty + j) * K + kb + tx] = tf32r(t[tx][ty + j]);
}

// ---------------- LayerNorm -> tf32-rounded plane ----------------
__global__ void __launch_bounds__(256) ln_k(const float* __restrict__ in,
                                            const float* __restrict__ gg,
                                            const float* __restrict__ bb,
                                            float* __restrict__ o,
                                            int windowed) {
    int blk = blockIdx.x;
    int src = windowed ? m_to_p(blk) : blk;
    const float* xr = in + (size_t)src * DIM;
    int t = threadIdx.x;
    float v0 = xr[t], v1 = xr[t + 256], v2 = xr[t + 512];
    float s = v0 + v1 + v2;
    float sq = v0 * v0 + v1 * v1 + v2 * v2;
#pragma unroll
    for (int off = 16; off > 0; off >>= 1) {
        s  += __shfl_xor_sync(0xffffffffu, s, off);
        sq += __shfl_xor_sync(0xffffffffu, sq, off);
    }
    __shared__ float sh[16];
    int wid = t >> 5, lane = t & 31;
    if (!lane) { sh[wid] = s; sh[8 + wid] = sq; }
    __syncthreads();
    float st = 0.f, sqt = 0.f;
#pragma unroll
    for (int i = 0; i < 8; i++) { st += sh[i]; sqt += sh[8 + i]; }
    float mu = st * (1.0f / 768.0f);
    float var = sqt * (1.0f / 768.0f) - mu * mu;
    float rstd = rsqrtf(var + 1e-5f);
    size_t base = (size_t)blk * DIM;
    o[base + t]       = tf32r((v0 - mu) * rstd * gg[t]       + bb[t]);
    o[base + t + 256] = tf32r((v1 - mu) * rstd * gg[t + 256] + bb[t + 256]);
    o[base + t + 512] = tf32r((v2 - mu) * rstd * gg[t + 512] + bb[t + 512]);
}

// ---------------- tf32 HMMA GEMM: C(MxN) = A(MxK) * B^T, B stored [N][K] ---
// Single-pass tf32 (operands pre-rounded). CTA 128x128, 8 warps of 32x64,
// k-chunk 32, 2-stage cp.async, 2 CTAs/SM.
// EPI: 0=+bias->f32  1=gelu(+bias)->tf32 plane  2=+bias+res scatter->f32  3=+bias+res->f32
#define ROWB 144                            // 128B data + 16B pad (conflict-free)
#define A_PL (128 * ROWB)                   // 18432
#define STAGE_BYTES (2 * A_PL)              // 36864
#define SMEM_GEMM (2 * STAGE_BYTES + 1024)  // 74752

template <int EPI>
__global__ void __launch_bounds__(256, 2)
tgemm_k(const float* __restrict__ A, const float* __restrict__ B,
        const float* __restrict__ bias, const float* __restrict__ res,
        float* __restrict__ C, float* __restrict__ Cr,
        int M, int N, int K) {
    extern __shared__ char dyn[];
    uint32_t sb = (smem_u32(dyn) + 255) & ~255u;

    const int tid = threadIdx.x, lane = tid & 31, wid = tid >> 5;
    const int bm = blockIdx.y * 128, bn = blockIdx.x * 128;
    const int wm = (wid >> 1) * 32, wn = (wid & 1) * 64;
    const int nk = K >> 5;

    // cp.async: 8 x 16B chunks/thread (A 1024 + B 1024 chunks; 32 f32/row)
    const float* gp[8]; uint32_t so[8];
#pragma unroll
    for (int q = 0; q < 8; q++) {
        int i = tid + q * 256;
        int isB = i >> 10, j = i & 1023, r = j >> 3, c = j & 7;
        gp[q] = (isB ? B + (size_t)(bn + r) * K : A + (size_t)(bm + r) * K) + c * 4;
        so[q] = (uint32_t)(isB * A_PL + r * ROWB + c * 16);
    }

    auto issue = [&](int stage, int t) {
        uint32_t s = sb + stage * STAGE_BYTES;
        int k0 = t * 32;
#pragma unroll
        for (int q = 0; q < 8; q++) cpa16(s + so[q], gp[q] + k0);
    };

    float acc[64];
#pragma unroll
    for (int i = 0; i < 64; i++) acc[i] = 0.f;

    // ldmatrix lane offsets
    const uint32_t aoff = (uint32_t)((((lane & 7) + ((lane >> 3) & 1) * 8) * ROWB) + (lane >> 4) * 16);
    const uint32_t boff = (uint32_t)((lane & 7) * ROWB + (lane >> 3) * 16);

    issue(0, 0); CP_COMMIT();
    issue(1, 1); CP_COMMIT();

    for (int t = 0; t < nk; ++t) {
        CP_WAIT1();
        __syncthreads();

        uint32_t s = sb + (t & 1) * STAGE_BYTES;
#pragma unroll
        for (int sp = 0; sp < 2; sp++) {
            // A fragments for ksteps 2sp, 2sp+1 (m16k8 tile = 1 ldmatrix.x4)
            uint32_t af[2][2][4];
#pragma unroll
            for (int ks = 0; ks < 2; ks++)
#pragma unroll
                for (int mi = 0; mi < 2; mi++)
                    ldx4(af[ks][mi], s + (uint32_t)((wm + mi * 16) * ROWB) + (sp * 2 + ks) * 32 + aoff);
#pragma unroll
            for (int p = 0; p < 8; p++) {
                uint32_t bf[4];   // n8 x k16: {b0,b1} kstep0, {b2,b3} kstep1
                ldx4(bf, s + A_PL + (uint32_t)((wn + p * 8) * ROWB) + sp * 64 + boff);
                mma1688t(&acc[(0 * 8 + p) * 4], af[0][0], bf);
                mma1688t(&acc[(1 * 8 + p) * 4], af[0][1], bf);
                mma1688t(&acc[(0 * 8 + p) * 4], af[1][0], bf + 2);
                mma1688t(&acc[(1 * 8 + p) * 4], af[1][1], bf + 2);
            }
        }

        __syncthreads();
        if (t + 2 < nk) issue(t & 1, t + 2);
        CP_COMMIT();
    }

    // -------- epilogue --------
#pragma unroll
    for (int mi = 0; mi < 2; mi++) {
        int r0 = bm + wm + mi * 16 + (lane >> 2);
#pragma unroll
        for (int ni = 0; ni < 8; ni++) {
            int gn = bn + wn + ni * 8 + (lane & 3) * 2;
            float* a = &acc[(mi * 8 + ni) * 4];
            float b0 = bias[gn], b1 = bias[gn + 1];
#pragma unroll
            for (int h = 0; h < 2; h++) {
                int row = r0 + h * 8;
                float x0 = a[h * 2] + b0, x1 = a[h * 2 + 1] + b1;
                if (EPI == 1) {
                    float g0 = 0.5f * x0 * (1.0f + erff(x0 * 0.70710678118654752f));
                    float g1 = 0.5f * x1 * (1.0f + erff(x1 * 0.70710678118654752f));
                    float2 o; o.x = tf32r(g0); o.y = tf32r(g1);
                    *(float2*)(Cr + (size_t)row * N + gn) = o;
                } else if (EPI == 2) {
                    int p = m_to_p(row);
                    const float* rp = res + (size_t)p * DIM + gn;
                    float2 o; o.x = x0 + rp[0]; o.y = x1 + rp[1];
                    *(float2*)(C + (size_t)p * DIM + gn) = o;
                } else if (EPI == 3) {
                    const float* rp = res + (size_t)row * N + gn;
                    float2 o; o.x = x0 + rp[0]; o.y = x1 + rp[1];
                    *(float2*)(C + (size_t)row * N + gn) = o;
                } else {
                    float2 o; o.x = x0; o.y = x1;
                    *(float2*)(C + (size_t)row * N + gn) = o;
                }
            }
        }
    }
}

// ---------------- window attention (fp32 in, tf32 plane out) ----------
#define ATTN_SMEM (2 * TOK * HDIM * 4)

__global__ void __launch_bounds__(224) attn_k(const float* __restrict__ qkv,
                                              const float* __restrict__ rph,
                                              const float* __restrict__ rpw,
                                              float* __restrict__ o) {
    extern __shared__ float sm[];
    float* Ks = sm;
    float* Vs = sm + TOK * HDIM;
    const int win = blockIdx.x, head = blockIdx.y;
    const int tid = threadIdx.x;
    const float* base = qkv + (size_t)win * TOK * (3 * DIM) + head * HDIM;

    for (int idx = tid; idx < TOK * 16; idx += 224) {
        int kt = idx >> 4, d4 = (idx & 15) << 2;
        *(float4*)&Ks[kt * HDIM + d4] = *(const float4*)(base + (size_t)kt * (3 * DIM) + DIM + d4);
        *(float4*)&Vs[kt * HDIM + d4] = *(const float4*)(base + (size_t)kt * (3 * DIM) + 2 * DIM + d4);
    }
    __syncthreads();
    if (tid >= TOK) return;

    const int qi = tid / WSZ, qj = tid - qi * WSZ;

    ull q2[32];
#pragma unroll
    for (int d = 0; d < HDIM; d += 4) {
        float4 t = *(const float4*)(base + (size_t)tid * (3 * DIM) + d);
        q2[(d >> 1)]     = pk2(t.x * 0.125f, t.y * 0.125f);
        q2[(d >> 1) + 1] = pk2(t.z * 0.125f, t.w * 0.125f);
    }

    float relh[WSZ], relw[WSZ];
#pragma unroll
    for (int kh = 0; kh < WSZ; kh++) {
        const ull* r1 = (const ull*)(rph + (size_t)(qi - kh + WSZ - 1) * HDIM);
        const ull* r2 = (const ull*)(rpw + (size_t)(qj - kh + WSZ - 1) * HDIM);
        ull a0 = 0, a1 = 0, b0 = 0, b1 = 0;
#pragma unroll
        for (int j = 0; j < 32; j += 2) {
            fma2(a0, q2[j], r1[j]); fma2(a1, q2[j + 1], r1[j + 1]);
            fma2(b0, q2[j], r2[j]); fma2(b1, q2[j + 1], r2[j + 1]);
        }
        float2 fa0 = upk2(a0), fa1 = upk2(a1), fb0 = upk2(b0), fb1 = upk2(b1);
        relh[kh] = 8.0f * (fa0.x + fa0.y + fa1.x + fa1.y);
        relw[kh] = 8.0f * (fb0.x + fb0.y + fb1.x + fb1.y);
    }

    ull acc[32];
#pragma unroll
    for (int j = 0; j < 32; j++) acc[j] = 0ull;
    float mmax = -INFINITY, l = 0.f;

    for (int kh = 0; kh < WSZ; kh++) {
        for (int kw = 0; kw < WSZ; kw++) {
            int kt = kh * WSZ + kw;
            const ull* kp = (const ull*)&Ks[kt * HDIM];
            ull s0 = 0, s1 = 0, s2 = 0, s3 = 0;
#pragma unroll
            for (int j = 0; j < 32; j += 4) {
                fma2(s0, q2[j],     kp[j]);
                fma2(s1, q2[j + 1], kp[j + 1]);
                fma2(s2, q2[j + 2], kp[j + 2]);
                fma2(s3, q2[j + 3], kp[j + 3]);
            }
            float2 f0 = upk2(s0), f1 = upk2(s1), f2 = upk2(s2), f3 = upk2(s3);
            float s = f0.x + f0.y + f1.x + f1.y + f2.x + f2.y + f3.x + f3.y
                    + relh[kh] + relw[kw];
            if (s > mmax) {
                float c = expf(mmax - s);
                l *= c;
                ull c2 = pk2(c, c);
#pragma unroll
                for (int j = 0; j < 32; j++) mul2(acc[j], acc[j], c2);
                mmax = s;
            }
            float p = expf(s - mmax);
            l += p;
            ull p2 = pk2(p, p);
            const ull* vp = (const ull*)&Vs[kt * HDIM];
#pragma unroll
            for (int j = 0; j < 32; j++) fma2(acc[j], p2, vp[j]);
        }
    }

    float inv = 1.0f / l;
    float* op = o + ((size_t)win * TOK + tid) * DIM + head * HDIM;
#pragma unroll
    for (int j = 0; j < 32; j++) {
        float2 f = upk2(acc[j]);
        float2 w; w.x = tf32r(f.x * inv); w.y = tf32r(f.y * inv);
        *(float2*)&op[2 * j] = w;
    }
}

// ---------------- launcher ----------------
extern "C" void kernel_launch(void* const* d_in, const int* in_sizes, int n_in,
                              void* d_out, int out_size) {
    const float* x     = (const float*)d_in[0];
    const float* n1g   = (const float*)d_in[1];
    const float* n1b   = (const float*)d_in[2];
    const float* qkvw  = (const float*)d_in[3];
    const float* qkvb  = (const float*)d_in[4];
    const float* projw = (const float*)d_in[5];
    const float* projb = (const float*)d_in[6];
    const float* rph   = (const float*)d_in[7];
    const float* rpw   = (const float*)d_in[8];
    const float* n2g   = (const float*)d_in[9];
    const float* n2b   = (const float*)d_in[10];
    const float* l1w   = (const float*)d_in[11];
    const float* l1b   = (const float*)d_in[12];
    const float* l2w   = (const float*)d_in[13];
    const float* l2b   = (const float*)d_in[14];
    float* out = (float*)d_out;

    cudaFuncSetAttribute(attn_k, cudaFuncAttributeMaxDynamicSharedMemorySize, ATTN_SMEM);
    cudaFuncSetAttribute(tgemm_k<0>, cudaFuncAttributeMaxDynamicSharedMemorySize, SMEM_GEMM);
    cudaFuncSetAttribute(tgemm_k<1>, cudaFuncAttributeMaxDynamicSharedMemorySize, SMEM_GEMM);
    cudaFuncSetAttribute(tgemm_k<2>, cudaFuncAttributeMaxDynamicSharedMemorySize, SMEM_GEMM);
    cudaFuncSetAttribute(tgemm_k<3>, cudaFuncAttributeMaxDynamicSharedMemorySize, SMEM_GEMM);

    float *p_a1, *p_qkv, *p_at, *p_hid, *p_a2, *p_h;
    float *p_wq, *p_wp, *p_w1, *p_w2;
    cudaGetSymbolAddress((void**)&p_a1,  g_a1);
    cudaGetSymbolAddress((void**)&p_qkv, g_qkv);
    cudaGetSymbolAddress((void**)&p_at,  g_at);
    cudaGetSymbolAddress((void**)&p_hid, g_hid);
    cudaGetSymbolAddress((void**)&p_a2,  g_a2);
    cudaGetSymbolAddress((void**)&p_h,   g_h);
    cudaGetSymbolAddress((void**)&p_wq,  g_wq);
    cudaGetSymbolAddress((void**)&p_wp,  g_wp);
    cudaGetSymbolAddress((void**)&p_w1,  g_w1);
    cudaGetSymbolAddress((void**)&p_w2,  g_w2);

    dim3 tb(32, 8);
    wprep_k<<<dim3(3 * DIM / 32, DIM / 32), tb>>>(qkvw,  p_wq, DIM,  3 * DIM);
    wprep_k<<<dim3(DIM / 32, DIM / 32),     tb>>>(projw, p_wp, DIM,  DIM);

    // 1) LN1 + window-partition -> tf32 plane
    ln_k<<<MROWS, 256>>>(x, n1g, n1b, p_a1, 1);

    // 2) QKV GEMM -> fp32 qkv   (50176 x 2304 x 768)
    tgemm_k<0><<<dim3(18, 392), 256, SMEM_GEMM>>>(p_a1, p_wq,
        qkvb, nullptr, p_qkv, nullptr, MROWS, 3 * DIM, DIM);

    // 3) attention -> tf32 plane
    attn_k<<<dim3(NWIN, NHD), 224, ATTN_SMEM>>>(p_qkv, rph, rpw, p_at);

    // 4) proj GEMM + unpartition + residual -> g_hid (fp32)   (50176 x 768 x 768)
    tgemm_k<2><<<dim3(6, 392), 256, SMEM_GEMM>>>(p_at, p_wp,
        projb, x, p_hid, nullptr, MROWS, DIM, DIM);

    // 5) LN2 -> tf32 plane
    ln_k<<<MROWS, 256>>>(p_hid, n2g, n2b, p_a2, 0);

    wprep_k<<<dim3(MLPD / 32, DIM / 32), tb>>>(l1w, p_w1, DIM, MLPD);

    // 6) MLP1 + gelu -> tf32 plane   (50176 x 3072 x 768)
    tgemm_k<1><<<dim3(24, 392), 256, SMEM_GEMM>>>(p_a2, p_w1,
        l1b, nullptr, nullptr, p_h, MROWS, MLPD, DIM);

    wprep_k<<<dim3(DIM / 32, MLPD / 32), tb>>>(l2w, p_w2, MLPD, DIM);

    // 7) MLP2 + residual -> out (fp32)   (50176 x 768 x 3072)
    tgemm_k<3><<<dim3(6, 392), 256, SMEM_GEMM>>>(p_h, p_w2,
        l2b, p_hid, out, nullptr, MROWS, DIM, MLPD);
}

// round 8
// speedup vs baseline: 1.5507x; 1.0317x over previous
#include <cuda_runtime.h>
#include <math.h>
#include <stdint.h>

// ---------------- problem constants ----------------
#define BQ    16
#define ISZ   56
#define DIM   768
#define NHD   12
#define HDIM  64
#define WSZ   14
#define TOK   196
#define NWIN  256
#define MROWS 50176
#define MLPD  3072

typedef unsigned long long ull;

// ---------------- scratch (device globals) ----------------
__device__ __align__(16) float g_a1 [(size_t)MROWS * DIM];
__device__ __align__(16) float g_qkv[(size_t)MROWS * 3 * DIM];
__device__ __align__(16) float g_at [(size_t)MROWS * DIM];
__device__ __align__(16) float g_hid[(size_t)MROWS * DIM];
__device__ __align__(16) float g_a2 [(size_t)MROWS * DIM];
__device__ __align__(16) float g_h  [(size_t)MROWS * MLPD];
// transposed tf32-rounded weights: T[n][k]
__device__ __align__(16) float g_wq[(size_t)(3 * DIM) * DIM];
__device__ __align__(16) float g_wp[(size_t)DIM * DIM];
__device__ __align__(16) float g_w1[(size_t)MLPD * DIM];
__device__ __align__(16) float g_w2[(size_t)DIM * MLPD];

// ---------------- helpers ----------------
__device__ __forceinline__ float tf32r(float x) {
    uint32_t u;
    asm("cvt.rna.tf32.f32 %0, %1;" : "=r"(u) : "f"(x));
    return __uint_as_float(u);
}
__device__ __forceinline__ uint32_t smem_u32(const void* p) {
    uint32_t a;
    asm("{ .reg .u64 t; cvta.to.shared.u64 t, %1; cvt.u32.u64 %0, t; }" : "=r"(a) : "l"(p));
    return a;
}

// f32x2 packed math (attention)
__device__ __forceinline__ ull pk2(float lo, float hi) {
    ull r; asm("mov.b64 %0, {%1, %2};" : "=l"(r) : "f"(lo), "f"(hi)); return r;
}
__device__ __forceinline__ float2 upk2(ull v) {
    float2 f; asm("mov.b64 {%0, %1}, %2;" : "=f"(f.x), "=f"(f.y) : "l"(v)); return f;
}
__device__ __forceinline__ void fma2(ull& c, ull a, ull b) {
    asm("fma.rn.f32x2 %0, %1, %2, %3;" : "=l"(c) : "l"(a), "l"(b), "l"(c));
}
__device__ __forceinline__ void mul2(ull& c, ull a, ull b) {
    asm("mul.rn.f32x2 %0, %1, %2;" : "=l"(c) : "l"(a), "l"(b));
}

// window-token row m -> flat pixel p
__device__ __forceinline__ int m_to_p(int m) {
    int win = m / TOK, tok = m - win * TOK;
    int b = win >> 4, wr = win & 15;
    int wh = wr >> 2, ww = wr & 3;
    int i = tok / WSZ, j = tok - i * WSZ;
    return (b * ISZ + wh * WSZ + i) * ISZ + ww * WSZ + j;
}

// ---------------- mma / ldmatrix / cp.async (base sm_80+ PTX) --------------
__device__ __forceinline__ void mma1688t(float* d, const uint32_t* a, const uint32_t* b) {
    asm volatile("mma.sync.aligned.m16n8k8.row.col.f32.tf32.tf32.f32 "
        "{%0,%1,%2,%3},{%4,%5,%6,%7},{%8,%9},{%0,%1,%2,%3};"
        : "+f"(d[0]), "+f"(d[1]), "+f"(d[2]), "+f"(d[3])
        : "r"(a[0]), "r"(a[1]), "r"(a[2]), "r"(a[3]), "r"(b[0]), "r"(b[1]));
}
__device__ __forceinline__ void ldx4(uint32_t* r, uint32_t addr) {
    asm volatile("ldmatrix.sync.aligned.m8n8.x4.shared.b16 {%0,%1,%2,%3}, [%4];"
        : "=r"(r[0]), "=r"(r[1]), "=r"(r[2]), "=r"(r[3]) : "r"(addr));
}
__device__ __forceinline__ void cpa16(uint32_t dst, const void* src) {
    asm volatile("cp.async.cg.shared.global [%0], [%1], 16;" :: "r"(dst), "l"(src));
}
#define CP_COMMIT() asm volatile("cp.async.commit_group;" ::: "memory")
#define CP_WAIT2()  asm volatile("cp.async.wait_group 2;" ::: "memory")

// ---------------- weight transpose -> tf32-rounded fp32 ----------------
__global__ void __launch_bounds__(256) wprep_k(const float* __restrict__ W,
                                               float* __restrict__ T,
                                               int K, int N) {
    __shared__ float t[32][33];
    int nb = blockIdx.x * 32, kb = blockIdx.y * 32;
    int tx = threadIdx.x, ty = threadIdx.y;
#pragma unroll
    for (int j = 0; j < 32; j += 8)
        t[ty + j][tx] = W[(size_t)(kb + ty + j) * N + nb + tx];
    __syncthreads();
#pragma unroll
    for (int j = 0; j < 32; j += 8)
        T[(size_t)(nb + ty + j) * K + kb + tx] = tf32r(t[tx][ty + j]);
}

// ---------------- LayerNorm -> tf32-rounded plane ----------------
__global__ void __launch_bounds__(256) ln_k(const float* __restrict__ in,
                                            const float* __restrict__ gg,
                                            const float* __restrict__ bb,
                                            float* __restrict__ o,
                                            int windowed) {
    int blk = blockIdx.x;
    int src = windowed ? m_to_p(blk) : blk;
    const float* xr = in + (size_t)src * DIM;
    int t = threadIdx.x;
    float v0 = xr[t], v1 = xr[t + 256], v2 = xr[t + 512];
    float s = v0 + v1 + v2;
    float sq = v0 * v0 + v1 * v1 + v2 * v2;
#pragma unroll
    for (int off = 16; off > 0; off >>= 1) {
        s  += __shfl_xor_sync(0xffffffffu, s, off);
        sq += __shfl_xor_sync(0xffffffffu, sq, off);
    }
    __shared__ float sh[16];
    int wid = t >> 5, lane = t & 31;
    if (!lane) { sh[wid] = s; sh[8 + wid] = sq; }
    __syncthreads();
    float st = 0.f, sqt = 0.f;
#pragma unroll
    for (int i = 0; i < 8; i++) { st += sh[i]; sqt += sh[8 + i]; }
    float mu = st * (1.0f / 768.0f);
    float var = sqt * (1.0f / 768.0f) - mu * mu;
    float rstd = rsqrtf(var + 1e-5f);
    size_t base = (size_t)blk * DIM;
    o[base + t]       = tf32r((v0 - mu) * rstd * gg[t]       + bb[t]);
    o[base + t + 256] = tf32r((v1 - mu) * rstd * gg[t + 256] + bb[t + 256]);
    o[base + t + 512] = tf32r((v2 - mu) * rstd * gg[t + 512] + bb[t + 512]);
}

// ---------------- tf32 HMMA GEMM: C(MxN) = A(MxK) * B^T, B stored [N][K] ---
// Single-pass tf32. CTA 128x128, 4 warps of 64x64 (LDSM:mma = 1:4),
// k-chunk 32, 3-stage cp.async, 2 CTAs/SM.
// EPI: 0=+bias->f32  1=gelu(+bias)->tf32 plane  2=+bias+res scatter->f32  3=+bias+res->f32
#define ROWB 144                            // 128B data + 16B pad (conflict-free)
#define A_PL (128 * ROWB)                   // 18432
#define STAGE_BYTES (2 * A_PL)              // 36864  (A + B)
#define SMEM_GEMM (3 * STAGE_BYTES + 256)   // 110848

template <int EPI>
__global__ void __launch_bounds__(128, 2)
tgemm_k(const float* __restrict__ A, const float* __restrict__ B,
        const float* __restrict__ bias, const float* __restrict__ res,
        float* __restrict__ C, float* __restrict__ Cr,
        int M, int N, int K) {
    extern __shared__ char dyn[];
    uint32_t sb = (smem_u32(dyn) + 255) & ~255u;

    const int tid = threadIdx.x, lane = tid & 31, wid = tid >> 5;
    const int bm = blockIdx.y * 128, bn = blockIdx.x * 128;
    const int wm = (wid >> 1) * 64, wn = (wid & 1) * 64;
    const int nk = K >> 5;

    // cp.async: 16 x 16B chunks/thread (A 1024 + B 1024 chunks; 32 f32/row)
    const float* gp[16]; uint32_t so[16];
#pragma unroll
    for (int q = 0; q < 16; q++) {
        int i = tid + q * 128;
        int isB = i >> 10, j = i & 1023, r = j >> 3, c = j & 7;
        gp[q] = (isB ? B + (size_t)(bn + r) * K : A + (size_t)(bm + r) * K) + c * 4;
        so[q] = (uint32_t)(isB * A_PL + r * ROWB + c * 16);
    }

    auto issue = [&](int stage, int t) {
        uint32_t s = sb + stage * STAGE_BYTES;
        int k0 = t * 32;
#pragma unroll
        for (int q = 0; q < 16; q++) cpa16(s + so[q], gp[q] + k0);
    };

    float acc[128];
#pragma unroll
    for (int i = 0; i < 128; i++) acc[i] = 0.f;

    // ldmatrix lane offsets
    const uint32_t aoff = (uint32_t)((((lane & 7) + ((lane >> 3) & 1) * 8) * ROWB) + (lane >> 4) * 16);
    const uint32_t boff = (uint32_t)((lane & 7) * ROWB + (lane >> 3) * 16);

    issue(0, 0); CP_COMMIT();
    issue(1, 1); CP_COMMIT();
    issue(2, 2); CP_COMMIT();

    for (int t = 0; t < nk; ++t) {
        CP_WAIT2();
        __syncthreads();

        uint32_t s = sb + (t % 3) * STAGE_BYTES;
#pragma unroll
        for (int sp = 0; sp < 2; sp++) {
            // A fragments: 4 m16-tiles x 2 ksteps (m16k8 per ldx4)
            uint32_t af[2][4][4];
#pragma unroll
            for (int ks = 0; ks < 2; ks++)
#pragma unroll
                for (int mi = 0; mi < 4; mi++)
                    ldx4(af[ks][mi], s + (uint32_t)((wm + mi * 16) * ROWB) + (sp * 2 + ks) * 32 + aoff);
#pragma unroll
            for (int p = 0; p < 8; p++) {
                uint32_t bf[4];   // n8 x k16: {b0,b1} kstep0, {b2,b3} kstep1
                ldx4(bf, s + A_PL + (uint32_t)((wn + p * 8) * ROWB) + sp * 64 + boff);
#pragma unroll
                for (int mi = 0; mi < 4; mi++)
                    mma1688t(&acc[(mi * 8 + p) * 4], af[0][mi], bf);
#pragma unroll
                for (int mi = 0; mi < 4; mi++)
                    mma1688t(&acc[(mi * 8 + p) * 4], af[1][mi], bf + 2);
            }
        }

        __syncthreads();
        if (t + 3 < nk) issue(t % 3, t + 3);
        CP_COMMIT();
    }

    // -------- epilogue --------
#pragma unroll
    for (int mi = 0; mi < 4; mi++) {
        int r0 = bm + wm + mi * 16 + (lane >> 2);
#pragma unroll
        for (int p = 0; p < 8; p++) {
            int gn = bn + wn + p * 8 + (lane & 3) * 2;
            float* a = &acc[(mi * 8 + p) * 4];
            float b0 = bias[gn], b1 = bias[gn + 1];
#pragma unroll
            for (int h = 0; h < 2; h++) {
                int row = r0 + h * 8;
                float x0 = a[h * 2] + b0, x1 = a[h * 2 + 1] + b1;
                if (EPI == 1) {
                    float g0 = 0.5f * x0 * (1.0f + erff(x0 * 0.70710678118654752f));
                    float g1 = 0.5f * x1 * (1.0f + erff(x1 * 0.70710678118654752f));
                    float2 o; o.x = tf32r(g0); o.y = tf32r(g1);
                    *(float2*)(Cr + (size_t)row * N + gn) = o;
                } else if (EPI == 2) {
                    int pp = m_to_p(row);
                    const float* rp = res + (size_t)pp * DIM + gn;
                    float2 o; o.x = x0 + rp[0]; o.y = x1 + rp[1];
                    *(float2*)(C + (size_t)pp * DIM + gn) = o;
                } else if (EPI == 3) {
                    const float* rp = res + (size_t)row * N + gn;
                    float2 o; o.x = x0 + rp[0]; o.y = x1 + rp[1];
                    *(float2*)(C + (size_t)row * N + gn) = o;
                } else {
                    float2 o; o.x = x0; o.y = x1;
                    *(float2*)(C + (size_t)row * N + gn) = o;
                }
            }
        }
    }
}

// ---------------- window attention (fp32 in, tf32 plane out) ----------
#define ATTN_SMEM (2 * TOK * HDIM * 4)

__global__ void __launch_bounds__(224) attn_k(const float* __restrict__ qkv,
                                              const float* __restrict__ rph,
                                              const float* __restrict__ rpw,
                                              float* __restrict__ o) {
    extern __shared__ float sm[];
    float* Ks = sm;
    float* Vs = sm + TOK * HDIM;
    const int win = blockIdx.x, head = blockIdx.y;
    const int tid = threadIdx.x;
    const float* base = qkv + (size_t)win * TOK * (3 * DIM) + head * HDIM;

    for (int idx = tid; idx < TOK * 16; idx += 224) {
        int kt = idx >> 4, d4 = (idx & 15) << 2;
        *(float4*)&Ks[kt * HDIM + d4] = *(const float4*)(base + (size_t)kt * (3 * DIM) + DIM + d4);
        *(float4*)&Vs[kt * HDIM + d4] = *(const float4*)(base + (size_t)kt * (3 * DIM) + 2 * DIM + d4);
    }
    __syncthreads();
    if (tid >= TOK) return;

    const int qi = tid / WSZ, qj = tid - qi * WSZ;

    ull q2[32];
#pragma unroll
    for (int d = 0; d < HDIM; d += 4) {
        float4 t = *(const float4*)(base + (size_t)tid * (3 * DIM) + d);
        q2[(d >> 1)]     = pk2(t.x * 0.125f, t.y * 0.125f);
        q2[(d >> 1) + 1] = pk2(t.z * 0.125f, t.w * 0.125f);
    }

    float relh[WSZ], relw[WSZ];
#pragma unroll
    for (int kh = 0; kh < WSZ; kh++) {
        const ull* r1 = (const ull*)(rph + (size_t)(qi - kh + WSZ - 1) * HDIM);
        const ull* r2 = (const ull*)(rpw + (size_t)(qj - kh + WSZ - 1) * HDIM);
        ull a0 = 0, a1 = 0, b0 = 0, b1 = 0;
#pragma unroll
        for (int j = 0; j < 32; j += 2) {
            fma2(a0, q2[j], r1[j]); fma2(a1, q2[j + 1], r1[j + 1]);
            fma2(b0, q2[j], r2[j]); fma2(b1, q2[j + 1], r2[j + 1]);
        }
        float2 fa0 = upk2(a0), fa1 = upk2(a1), fb0 = upk2(b0), fb1 = upk2(b1);
        relh[kh] = 8.0f * (fa0.x + fa0.y + fa1.x + fa1.y);
        relw[kh] = 8.0f * (fb0.x + fb0.y + fb1.x + fb1.y);
    }

    ull acc[32];
#pragma unroll
    for (int j = 0; j < 32; j++) acc[j] = 0ull;
    float mmax = -INFINITY, l = 0.f;

    for (int kh = 0; kh < WSZ; kh++) {
        for (int kw = 0; kw < WSZ; kw++) {
            int kt = kh * WSZ + kw;
            const ull* kp = (const ull*)&Ks[kt * HDIM];
            ull s0 = 0, s1 = 0, s2 = 0, s3 = 0;
#pragma unroll
            for (int j = 0; j < 32; j += 4) {
                fma2(s0, q2[j],     kp[j]);
                fma2(s1, q2[j + 1], kp[j + 1]);
                fma2(s2, q2[j + 2], kp[j + 2]);
                fma2(s3, q2[j + 3], kp[j + 3]);
            }
            float2 f0 = upk2(s0), f1 = upk2(s1), f2 = upk2(s2), f3 = upk2(s3);
            float s = f0.x + f0.y + f1.x + f1.y + f2.x + f2.y + f3.x + f3.y
                    + relh[kh] + relw[kw];
            if (s > mmax) {
                float c = __expf(mmax - s);
                l *= c;
                ull c2 = pk2(c, c);
#pragma unroll
                for (int j = 0; j < 32; j++) mul2(acc[j], acc[j], c2);
                mmax = s;
            }
            float p = __expf(s - mmax);
            l += p;
            ull p2 = pk2(p, p);
            const ull* vp = (const ull*)&Vs[kt * HDIM];
#pragma unroll
            for (int j = 0; j < 32; j++) fma2(acc[j], p2, vp[j]);
        }
    }

    float inv = 1.0f / l;
    float* op = o + ((size_t)win * TOK + tid) * DIM + head * HDIM;
#pragma unroll
    for (int j = 0; j < 32; j++) {
        float2 f = upk2(acc[j]);
        float2 w; w.x = tf32r(f.x * inv); w.y = tf32r(f.y * inv);
        *(float2*)&op[2 * j] = w;
    }
}

// ---------------- launcher ----------------
extern "C" void kernel_launch(void* const* d_in, const int* in_sizes, int n_in,
                              void* d_out, int out_size) {
    const float* x     = (const float*)d_in[0];
    const float* n1g   = (const float*)d_in[1];
    const float* n1b   = (const float*)d_in[2];
    const float* qkvw  = (const float*)d_in[3];
    const float* qkvb  = (const float*)d_in[4];
    const float* projw = (const float*)d_in[5];
    const float* projb = (const float*)d_in[6];
    const float* rph   = (const float*)d_in[7];
    const float* rpw   = (const float*)d_in[8];
    const float* n2g   = (const float*)d_in[9];
    const float* n2b   = (const float*)d_in[10];
    const float* l1w   = (const float*)d_in[11];
    const float* l1b   = (const float*)d_in[12];
    const float* l2w   = (const float*)d_in[13];
    const float* l2b   = (const float*)d_in[14];
    float* out = (float*)d_out;

    cudaFuncSetAttribute(attn_k, cudaFuncAttributeMaxDynamicSharedMemorySize, ATTN_SMEM);
    cudaFuncSetAttribute(tgemm_k<0>, cudaFuncAttributeMaxDynamicSharedMemorySize, SMEM_GEMM);
    cudaFuncSetAttribute(tgemm_k<1>, cudaFuncAttributeMaxDynamicSharedMemorySize, SMEM_GEMM);
    cudaFuncSetAttribute(tgemm_k<2>, cudaFuncAttributeMaxDynamicSharedMemorySize, SMEM_GEMM);
    cudaFuncSetAttribute(tgemm_k<3>, cudaFuncAttributeMaxDynamicSharedMemorySize, SMEM_GEMM);

    float *p_a1, *p_qkv, *p_at, *p_hid, *p_a2, *p_h;
    float *p_wq, *p_wp, *p_w1, *p_w2;
    cudaGetSymbolAddress((void**)&p_a1,  g_a1);
    cudaGetSymbolAddress((void**)&p_qkv, g_qkv);
    cudaGetSymbolAddress((void**)&p_at,  g_at);
    cudaGetSymbolAddress((void**)&p_hid, g_hid);
    cudaGetSymbolAddress((void**)&p_a2,  g_a2);
    cudaGetSymbolAddress((void**)&p_h,   g_h);
    cudaGetSymbolAddress((void**)&p_wq,  g_wq);
    cudaGetSymbolAddress((void**)&p_wp,  g_wp);
    cudaGetSymbolAddress((void**)&p_w1,  g_w1);
    cudaGetSymbolAddress((void**)&p_w2,  g_w2);

    dim3 tb(32, 8);
    wprep_k<<<dim3(3 * DIM / 32, DIM / 32), tb>>>(qkvw,  p_wq, DIM,  3 * DIM);
    wprep_k<<<dim3(DIM / 32, DIM / 32),     tb>>>(projw, p_wp, DIM,  DIM);

    // 1) LN1 + window-partition -> tf32 plane
    ln_k<<<MROWS, 256>>>(x, n1g, n1b, p_a1, 1);

    // 2) QKV GEMM -> fp32 qkv   (50176 x 2304 x 768)
    tgemm_k<0><<<dim3(18, 392), 128, SMEM_GEMM>>>(p_a1, p_wq,
        qkvb, nullptr, p_qkv, nullptr, MROWS, 3 * DIM, DIM);

    // 3) attention -> tf32 plane
    attn_k<<<dim3(NWIN, NHD), 224, ATTN_SMEM>>>(p_qkv, rph, rpw, p_at);

    // 4) proj GEMM + unpartition + residual -> g_hid (fp32)   (50176 x 768 x 768)
    tgemm_k<2><<<dim3(6, 392), 128, SMEM_GEMM>>>(p_at, p_wp,
        projb, x, p_hid, nullptr, MROWS, DIM, DIM);

    // 5) LN2 -> tf32 plane
    ln_k<<<MROWS, 256>>>(p_hid, n2g, n2b, p_a2, 0);

    wprep_k<<<dim3(MLPD / 32, DIM / 32), tb>>>(l1w, p_w1, DIM, MLPD);

    // 6) MLP1 + gelu -> tf32 plane   (50176 x 3072 x 768)
    tgemm_k<1><<<dim3(24, 392), 128, SMEM_GEMM>>>(p_a2, p_w1,
        l1b, nullptr, nullptr, p_h, MROWS, MLPD, DIM);

    wprep_k<<<dim3(DIM / 32, MLPD / 32), tb>>>(l2w, p_w2, MLPD, DIM);

    // 7) MLP2 + residual -> out (fp32)   (50176 x 768 x 3072)
    tgemm_k<3><<<dim3(6, 392), 128, SMEM_GEMM>>>(p_h, p_w2,
        l2b, p_hid, out, nullptr, MROWS, DIM, MLPD);
}

// round 10
// speedup vs baseline: 2.1395x; 1.3797x over previous
#include <cuda_runtime.h>
#include <math.h>
#include <stdint.h>

// ---------------- problem constants ----------------
#define BQ    16
#define ISZ   56
#define DIM   768
#define NHD   12
#define HDIM  64
#define WSZ   14
#define TOK   196
#define NWIN  256
#define MROWS 50176
#define MLPD  3072

typedef unsigned long long ull;

// ---------------- scratch (device globals) ----------------
__device__ __align__(16) float g_a1 [(size_t)MROWS * DIM];
__device__ __align__(16) float g_qkv[(size_t)MROWS * 3 * DIM];
__device__ __align__(16) float g_at [(size_t)MROWS * DIM];
__device__ __align__(16) float g_hid[(size_t)MROWS * DIM];
__device__ __align__(16) float g_a2 [(size_t)MROWS * DIM];
__device__ __align__(16) float g_h  [(size_t)MROWS * MLPD];
// transposed tf32-rounded weights: T[n][k]
__device__ __align__(16) float g_wq[(size_t)(3 * DIM) * DIM];
__device__ __align__(16) float g_wp[(size_t)DIM * DIM];
__device__ __align__(16) float g_w1[(size_t)MLPD * DIM];
__device__ __align__(16) float g_w2[(size_t)DIM * MLPD];

// ---------------- helpers ----------------
__device__ __forceinline__ float tf32r(float x) {
    uint32_t u;
    asm("cvt.rna.tf32.f32 %0, %1;" : "=r"(u) : "f"(x));
    return __uint_as_float(u);
}
__device__ __forceinline__ uint32_t smem_u32(const void* p) {
    uint32_t a;
    asm("{ .reg .u64 t; cvta.to.shared.u64 t, %1; cvt.u32.u64 %0, t; }" : "=r"(a) : "l"(p));
    return a;
}

// f32x2 packed math
__device__ __forceinline__ ull pk2(float lo, float hi) {
    ull r; asm("mov.b64 %0, {%1, %2};" : "=l"(r) : "f"(lo), "f"(hi)); return r;
}
__device__ __forceinline__ float2 upk2(ull v) {
    float2 f; asm("mov.b64 {%0, %1}, %2;" : "=f"(f.x), "=f"(f.y) : "l"(v)); return f;
}
__device__ __forceinline__ void fma2(ull& c, ull a, ull b) {
    asm("fma.rn.f32x2 %0, %1, %2, %3;" : "=l"(c) : "l"(a), "l"(b), "l"(c));
}

// window-token row m -> flat pixel p
__device__ __forceinline__ int m_to_p(int m) {
    int win = m / TOK, tok = m - win * TOK;
    int b = win >> 4, wr = win & 15;
    int wh = wr >> 2, ww = wr & 3;
    int i = tok / WSZ, j = tok - i * WSZ;
    return (b * ISZ + wh * WSZ + i) * ISZ + ww * WSZ + j;
}

__device__ __forceinline__ int div14(int x) { return (x * 37450) >> 19; }   // valid x < 256

// ---------------- mma / ldmatrix / cp.async (base sm_80+ PTX) --------------
__device__ __forceinline__ void mma1688t(float* d, const uint32_t* a, const uint32_t* b) {
    asm volatile("mma.sync.aligned.m16n8k8.row.col.f32.tf32.tf32.f32 "
        "{%0,%1,%2,%3},{%4,%5,%6,%7},{%8,%9},{%0,%1,%2,%3};"
        : "+f"(d[0]), "+f"(d[1]), "+f"(d[2]), "+f"(d[3])
        : "r"(a[0]), "r"(a[1]), "r"(a[2]), "r"(a[3]), "r"(b[0]), "r"(b[1]));
}
__device__ __forceinline__ void ldx4(uint32_t* r, uint32_t addr) {
    asm volatile("ldmatrix.sync.aligned.m8n8.x4.shared.b16 {%0,%1,%2,%3}, [%4];"
        : "=r"(r[0]), "=r"(r[1]), "=r"(r[2]), "=r"(r[3]) : "r"(addr));
}
__device__ __forceinline__ void cpa16(uint32_t dst, const void* src) {
    asm volatile("cp.async.cg.shared.global [%0], [%1], 16;" :: "r"(dst), "l"(src));
}
#define CP_COMMIT() asm volatile("cp.async.commit_group;" ::: "memory")
#define CP_WAIT2()  asm volatile("cp.async.wait_group 2;" ::: "memory")

// ---------------- weight transpose -> tf32-rounded fp32 ----------------
__global__ void __launch_bounds__(256) wprep_k(const float* __restrict__ W,
                                               float* __restrict__ T,
                                               int K, int N) {
    __shared__ float t[32][33];
    int nb = blockIdx.x * 32, kb = blockIdx.y * 32;
    int tx = threadIdx.x, ty = threadIdx.y;
#pragma unroll
    for (int j = 0; j < 32; j += 8)
        t[ty + j][tx] = W[(size_t)(kb + ty + j) * N + nb + tx];
    __syncthreads();
#pragma unroll
    for (int j = 0; j < 32; j += 8)
        T[(size_t)(nb + ty + j) * K + kb + tx] = tf32r(t[tx][ty + j]);
}

// ---------------- LayerNorm -> tf32-rounded plane ----------------
__global__ void __launch_bounds__(256) ln_k(const float* __restrict__ in,
                                            const float* __restrict__ gg,
                                            const float* __restrict__ bb,
                                            float* __restrict__ o,
                                            int windowed) {
    int blk = blockIdx.x;
    int src = windowed ? m_to_p(blk) : blk;
    const float* xr = in + (size_t)src * DIM;
    int t = threadIdx.x;
    float v0 = xr[t], v1 = xr[t + 256], v2 = xr[t + 512];
    float s = v0 + v1 + v2;
    float sq = v0 * v0 + v1 * v1 + v2 * v2;
#pragma unroll
    for (int off = 16; off > 0; off >>= 1) {
        s  += __shfl_xor_sync(0xffffffffu, s, off);
        sq += __shfl_xor_sync(0xffffffffu, sq, off);
    }
    __shared__ float sh[16];
    int wid = t >> 5, lane = t & 31;
    if (!lane) { sh[wid] = s; sh[8 + wid] = sq; }
    __syncthreads();
    float st = 0.f, sqt = 0.f;
#pragma unroll
    for (int i = 0; i < 8; i++) { st += sh[i]; sqt += sh[8 + i]; }
    float mu = st * (1.0f / 768.0f);
    float var = sqt * (1.0f / 768.0f) - mu * mu;
    float rstd = rsqrtf(var + 1e-5f);
    size_t base = (size_t)blk * DIM;
    o[base + t]       = tf32r((v0 - mu) * rstd * gg[t]       + bb[t]);
    o[base + t + 256] = tf32r((v1 - mu) * rstd * gg[t + 256] + bb[t + 256]);
    o[base + t + 512] = tf32r((v2 - mu) * rstd * gg[t + 512] + bb[t + 512]);
}

// ---------------- tf32 HMMA GEMM (unchanged from R8) ----------------------
#define ROWB 144
#define A_PL (128 * ROWB)
#define STAGE_BYTES (2 * A_PL)
#define SMEM_GEMM (3 * STAGE_BYTES + 256)

template <int EPI>
__global__ void __launch_bounds__(128, 2)
tgemm_k(const float* __restrict__ A, const float* __restrict__ B,
        const float* __restrict__ bias, const float* __restrict__ res,
        float* __restrict__ C, float* __restrict__ Cr,
        int M, int N, int K) {
    extern __shared__ char dyn[];
    uint32_t sb = (smem_u32(dyn) + 255) & ~255u;

    const int tid = threadIdx.x, lane = tid & 31, wid = tid >> 5;
    const int bm = blockIdx.y * 128, bn = blockIdx.x * 128;
    const int wm = (wid >> 1) * 64, wn = (wid & 1) * 64;
    const int nk = K >> 5;

    const float* gp[16]; uint32_t so[16];
#pragma unroll
    for (int q = 0; q < 16; q++) {
        int i = tid + q * 128;
        int isB = i >> 10, j = i & 1023, r = j >> 3, c = j & 7;
        gp[q] = (isB ? B + (size_t)(bn + r) * K : A + (size_t)(bm + r) * K) + c * 4;
        so[q] = (uint32_t)(isB * A_PL + r * ROWB + c * 16);
    }

    auto issue = [&](int stage, int t) {
        uint32_t s = sb + stage * STAGE_BYTES;
        int k0 = t * 32;
#pragma unroll
        for (int q = 0; q < 16; q++) cpa16(s + so[q], gp[q] + k0);
    };

    float acc[128];
#pragma unroll
    for (int i = 0; i < 128; i++) acc[i] = 0.f;

    const uint32_t aoff = (uint32_t)((((lane & 7) + ((lane >> 3) & 1) * 8) * ROWB) + (lane >> 4) * 16);
    const uint32_t boff = (uint32_t)((lane & 7) * ROWB + (lane >> 3) * 16);

    issue(0, 0); CP_COMMIT();
    issue(1, 1); CP_COMMIT();
    issue(2, 2); CP_COMMIT();

    for (int t = 0; t < nk; ++t) {
        CP_WAIT2();
        __syncthreads();

        uint32_t s = sb + (t % 3) * STAGE_BYTES;
#pragma unroll
        for (int sp = 0; sp < 2; sp++) {
            uint32_t af[2][4][4];
#pragma unroll
            for (int ks = 0; ks < 2; ks++)
#pragma unroll
                for (int mi = 0; mi < 4; mi++)
                    ldx4(af[ks][mi], s + (uint32_t)((wm + mi * 16) * ROWB) + (sp * 2 + ks) * 32 + aoff);
#pragma unroll
            for (int p = 0; p < 8; p++) {
                uint32_t bf[4];
                ldx4(bf, s + A_PL + (uint32_t)((wn + p * 8) * ROWB) + sp * 64 + boff);
#pragma unroll
                for (int mi = 0; mi < 4; mi++)
                    mma1688t(&acc[(mi * 8 + p) * 4], af[0][mi], bf);
#pragma unroll
                for (int mi = 0; mi < 4; mi++)
                    mma1688t(&acc[(mi * 8 + p) * 4], af[1][mi], bf + 2);
            }
        }

        __syncthreads();
        if (t + 3 < nk) issue(t % 3, t + 3);
        CP_COMMIT();
    }

#pragma unroll
    for (int mi = 0; mi < 4; mi++) {
        int r0 = bm + wm + mi * 16 + (lane >> 2);
#pragma unroll
        for (int p = 0; p < 8; p++) {
            int gn = bn + wn + p * 8 + (lane & 3) * 2;
            float* a = &acc[(mi * 8 + p) * 4];
            float b0 = bias[gn], b1 = bias[gn + 1];
#pragma unroll
            for (int h = 0; h < 2; h++) {
                int row = r0 + h * 8;
                float x0 = a[h * 2] + b0, x1 = a[h * 2 + 1] + b1;
                if (EPI == 1) {
                    float g0 = 0.5f * x0 * (1.0f + erff(x0 * 0.70710678118654752f));
                    float g1 = 0.5f * x1 * (1.0f + erff(x1 * 0.70710678118654752f));
                    float2 o; o.x = tf32r(g0); o.y = tf32r(g1);
                    *(float2*)(Cr + (size_t)row * N + gn) = o;
                } else if (EPI == 2) {
                    int pp = m_to_p(row);
                    const float* rp = res + (size_t)pp * DIM + gn;
                    float2 o; o.x = x0 + rp[0]; o.y = x1 + rp[1];
                    *(float2*)(C + (size_t)pp * DIM + gn) = o;
                } else if (EPI == 3) {
                    const float* rp = res + (size_t)row * N + gn;
                    float2 o; o.x = x0 + rp[0]; o.y = x1 + rp[1];
                    *(float2*)(C + (size_t)row * N + gn) = o;
                } else {
                    float2 o; o.x = x0; o.y = x1;
                    *(float2*)(C + (size_t)row * N + gn) = o;
                }
            }
        }
    }
}

// ---------------- fused tf32-MMA window attention --------------------------
// One CTA per (window, head). 128 threads (4 warps).
#define AT_KROW 272
#define AT_VROW 848
#define AT_SM_K  0
#define AT_SM_V  (200 * AT_KROW)                   // 54400
#define AT_SM_T1 (AT_SM_V + 64 * AT_VROW)          // 108672
#define AT_SM_T2 (AT_SM_T1 + 208 * 28 * 4)         // 131968
#define AT_SM_Q  (AT_SM_T2 + 208 * 28 * 4)         // 155264
#define AT_SMEM  (AT_SM_Q + 4 * 16 * AT_KROW)      // 172672

// build m16k8 A-fragment of P from S-acc layout via quad shuffles
__device__ __forceinline__ void pfrag(const float* s4, uint32_t* a, int lane) {
    int j0 = lane & 3;
    int sA = (lane & ~3) | (j0 >> 1);
    float c0lo = __shfl_sync(0xffffffffu, s4[0], sA);
    float c1lo = __shfl_sync(0xffffffffu, s4[1], sA);
    float c2lo = __shfl_sync(0xffffffffu, s4[2], sA);
    float c3lo = __shfl_sync(0xffffffffu, s4[3], sA);
    float c0hi = __shfl_sync(0xffffffffu, s4[0], sA + 2);
    float c1hi = __shfl_sync(0xffffffffu, s4[1], sA + 2);
    float c2hi = __shfl_sync(0xffffffffu, s4[2], sA + 2);
    float c3hi = __shfl_sync(0xffffffffu, s4[3], sA + 2);
    bool odd = (j0 & 1) != 0;
    a[0] = __float_as_uint(odd ? c1lo : c0lo);
    a[1] = __float_as_uint(odd ? c3lo : c2lo);
    a[2] = __float_as_uint(odd ? c1hi : c0hi);
    a[3] = __float_as_uint(odd ? c3hi : c2hi);
}

__global__ void __launch_bounds__(128) attn_k(const float* __restrict__ qkv,
                                              const float* __restrict__ rph,
                                              const float* __restrict__ rpw,
                                              float* __restrict__ o) {
    extern __shared__ char sm[];
    uint32_t sb = smem_u32(sm);
    const int win = blockIdx.x, head = blockIdx.y;
    const int tid = threadIdx.x, lane = tid & 31, wid = tid >> 5;
    const float* base = qkv + (size_t)win * TOK * (3 * DIM) + head * HDIM;

    // ---- K (keys 0..199; pad rows zero), tf32-rounded ----
    for (int i = tid; i < 200 * 16; i += 128) {
        int r = i >> 4, c4 = (i & 15) << 2;
        float4 v = make_float4(0.f, 0.f, 0.f, 0.f);
        if (r < TOK) v = *(const float4*)(base + (size_t)r * (3 * DIM) + DIM + c4);
        float4 w; w.x = tf32r(v.x); w.y = tf32r(v.y); w.z = tf32r(v.z); w.w = tf32r(v.w);
        *(float4*)(sm + AT_SM_K + r * AT_KROW + c4 * 4) = w;
    }
    // ---- V transposed: V^T[dim][key] ----
    for (int r = tid; r < TOK; r += 128) {
        const float* src = base + (size_t)r * (3 * DIM) + 2 * DIM;
#pragma unroll
        for (int d4 = 0; d4 < HDIM; d4 += 4) {
            float4 v = *(const float4*)(src + d4);
            *(float*)(sm + AT_SM_V + (d4 + 0) * AT_VROW + r * 4) = tf32r(v.x);
            *(float*)(sm + AT_SM_V + (d4 + 1) * AT_VROW + r * 4) = tf32r(v.y);
            *(float*)(sm + AT_SM_V + (d4 + 2) * AT_VROW + r * 4) = tf32r(v.z);
            *(float*)(sm + AT_SM_V + (d4 + 3) * AT_VROW + r * 4) = tf32r(v.w);
        }
    }
    // zero V^T pad keys 196..199
    for (int i = tid; i < 64 * 4; i += 128) {
        int r = i >> 2, c = 196 + (i & 3);
        *(float*)(sm + AT_SM_V + r * AT_VROW + c * 4) = 0.f;
    }
    // ---- bias tables T1[q][idx] = q . rph[idx], T2 likewise ----
    for (int q = tid; q < 208; q += 128) {
        float* t1 = (float*)(sm + AT_SM_T1) + q * 28;
        float* t2 = (float*)(sm + AT_SM_T2) + q * 28;
        if (q < TOK) {
            ull qr[32];
#pragma unroll
            for (int d = 0; d < HDIM; d += 4) {
                float4 v = *(const float4*)(base + (size_t)q * (3 * DIM) + d);
                qr[d >> 1]       = pk2(v.x, v.y);
                qr[(d >> 1) + 1] = pk2(v.z, v.w);
            }
            for (int idx = 0; idx < 27; idx++) {
                const ull* r1 = (const ull*)(rph + (size_t)idx * HDIM);
                const ull* r2 = (const ull*)(rpw + (size_t)idx * HDIM);
                ull a0 = 0, a1 = 0, b0 = 0, b1 = 0;
#pragma unroll
                for (int j = 0; j < 32; j += 2) {
                    fma2(a0, qr[j], r1[j]); fma2(a1, qr[j + 1], r1[j + 1]);
                    fma2(b0, qr[j], r2[j]); fma2(b1, qr[j + 1], r2[j + 1]);
                }
                float2 fa0 = upk2(a0), fa1 = upk2(a1), fb0 = upk2(b0), fb1 = upk2(b1);
                t1[idx] = fa0.x + fa0.y + fa1.x + fa1.y;
                t2[idx] = fb0.x + fb0.y + fb1.x + fb1.y;
            }
        } else {
            for (int idx = 0; idx < 28; idx++) { t1[idx] = 0.f; t2[idx] = 0.f; }
        }
    }
    __syncthreads();

    const uint32_t aoff  = (uint32_t)((((lane & 7) + ((lane >> 3) & 1) * 8) * AT_KROW) + (lane >> 4) * 16);
    const uint32_t boffK = (uint32_t)((lane & 7) * AT_KROW + (lane >> 3) * 16);
    const uint32_t boffV = (uint32_t)((lane & 7) * AT_VROW + (lane >> 3) * 16);
    const uint32_t qstage = sb + AT_SM_Q + wid * 16 * AT_KROW;

    for (int mt = wid; mt < 13; mt += 4) {
        const int mrow0 = mt * 16;
        // stage Q tile (scaled, tf32-rounded; clamp pad rows)
        for (int i = lane; i < 16 * 16; i += 32) {
            int r = i >> 4, c4 = (i & 15) << 2;
            int gr = mrow0 + r; if (gr > TOK - 1) gr = TOK - 1;
            float4 v = *(const float4*)(base + (size_t)gr * (3 * DIM) + c4);
            float4 w; w.x = tf32r(v.x * 0.125f); w.y = tf32r(v.y * 0.125f);
            w.z = tf32r(v.z * 0.125f); w.w = tf32r(v.w * 0.125f);
            *(float4*)(sm + AT_SM_Q + wid * 16 * AT_KROW + r * AT_KROW + c4 * 4) = w;
        }
        __syncwarp();
        uint32_t qf[8][4];
#pragma unroll
        for (int ks = 0; ks < 8; ks++) ldx4(qf[ks], qstage + ks * 32 + aoff);

        // ---- S = Qs @ K^T (25 n-tiles). Each j covers dims 16j..16j+15 -> j*64 bytes.
        float sc[25][4];
#pragma unroll
        for (int nt = 0; nt < 25; nt++) { sc[nt][0] = 0.f; sc[nt][1] = 0.f; sc[nt][2] = 0.f; sc[nt][3] = 0.f; }
#pragma unroll
        for (int j = 0; j < 4; j++) {
#pragma unroll
            for (int nt = 0; nt < 25; nt++) {
                uint32_t bf[4];
                ldx4(bf, sb + AT_SM_K + (uint32_t)(nt * 8 * AT_KROW) + j * 64 + boffK);
                mma1688t(sc[nt], qf[2 * j], bf);
                mma1688t(sc[nt], qf[2 * j + 1], bf + 2);
            }
        }

        // ---- bias + mask + softmax (exact, full row in regs) ----
        const int rA = mrow0 + (lane >> 2), rB = rA + 8;
        const int qiA = div14(rA), qjA = rA - qiA * 14;
        const int qiB = div14(rB), qjB = rB - qiB * 14;
        const float* T1A = (const float*)(sm + AT_SM_T1) + rA * 28 + qiA + 13;
        const float* T2A = (const float*)(sm + AT_SM_T2) + rA * 28 + qjA + 13;
        const float* T1B = (const float*)(sm + AT_SM_T1) + rB * 28 + qiB + 13;
        const float* T2B = (const float*)(sm + AT_SM_T2) + rB * 28 + qjB + 13;
        float mxA = -3e38f, mxB = -3e38f;
#pragma unroll
        for (int nt = 0; nt < 25; nt++) {
            int c0 = nt * 8 + 2 * (lane & 3), c1 = c0 + 1;
            int cc0 = c0 > 195 ? 195 : c0, cc1 = c1 > 195 ? 195 : c1;
            int kh0 = div14(cc0), kw0 = cc0 - kh0 * 14;
            int kh1 = div14(cc1), kw1 = cc1 - kh1 * 14;
            sc[nt][0] = (c0 < TOK) ? sc[nt][0] + T1A[-kh0] + T2A[-kw0] : -3e38f;
            sc[nt][1] = (c1 < TOK) ? sc[nt][1] + T1A[-kh1] + T2A[-kw1] : -3e38f;
            sc[nt][2] = (c0 < TOK) ? sc[nt][2] + T1B[-kh0] + T2B[-kw0] : -3e38f;
            sc[nt][3] = (c1 < TOK) ? sc[nt][3] + T1B[-kh1] + T2B[-kw1] : -3e38f;
            mxA = fmaxf(mxA, fmaxf(sc[nt][0], sc[nt][1]));
            mxB = fmaxf(mxB, fmaxf(sc[nt][2], sc[nt][3]));
        }
        mxA = fmaxf(mxA, __shfl_xor_sync(0xffffffffu, mxA, 1));
        mxA = fmaxf(mxA, __shfl_xor_sync(0xffffffffu, mxA, 2));
        mxB = fmaxf(mxB, __shfl_xor_sync(0xffffffffu, mxB, 1));
        mxB = fmaxf(mxB, __shfl_xor_sync(0xffffffffu, mxB, 2));
        float lA = 0.f, lB = 0.f;
#pragma unroll
        for (int nt = 0; nt < 25; nt++) {
            float p0 = __expf(sc[nt][0] - mxA);
            float p1 = __expf(sc[nt][1] - mxA);
            float p2 = __expf(sc[nt][2] - mxB);
            float p3 = __expf(sc[nt][3] - mxB);
            lA += p0 + p1; lB += p2 + p3;
            sc[nt][0] = tf32r(p0); sc[nt][1] = tf32r(p1);
            sc[nt][2] = tf32r(p2); sc[nt][3] = tf32r(p3);
        }
        lA += __shfl_xor_sync(0xffffffffu, lA, 1);
        lA += __shfl_xor_sync(0xffffffffu, lA, 2);
        lB += __shfl_xor_sync(0xffffffffu, lB, 1);
        lB += __shfl_xor_sync(0xffffffffu, lB, 2);

        // ---- O = P @ V (8 dim-tiles) ----
        float oa[8][4];
#pragma unroll
        for (int nt8 = 0; nt8 < 8; nt8++) { oa[nt8][0] = 0.f; oa[nt8][1] = 0.f; oa[nt8][2] = 0.f; oa[nt8][3] = 0.f; }
#pragma unroll
        for (int cp = 0; cp < 12; cp++) {
            uint32_t pa0[4], pa1[4];
            pfrag(sc[2 * cp], pa0, lane);
            pfrag(sc[2 * cp + 1], pa1, lane);
#pragma unroll
            for (int nt8 = 0; nt8 < 8; nt8++) {
                uint32_t bf[4];
                ldx4(bf, sb + AT_SM_V + (uint32_t)(nt8 * 8 * AT_VROW) + cp * 64 + boffV);
                mma1688t(oa[nt8], pa0, bf);
                mma1688t(oa[nt8], pa1, bf + 2);
            }
        }
        {   // tail chunk 24 (keys 192..199)
            uint32_t pa[4];
            pfrag(sc[24], pa, lane);
#pragma unroll
            for (int nt8 = 0; nt8 < 8; nt8++) {
                uint32_t bf[4];
                ldx4(bf, sb + AT_SM_V + (uint32_t)(nt8 * 8 * AT_VROW) + 12 * 64 + boffV);
                mma1688t(oa[nt8], pa, bf);
            }
        }

        // ---- normalize + store ----
        float invA = 1.f / lA, invB = 1.f / lB;
        if (rA < TOK) {
            float* dst = o + ((size_t)(win * TOK + rA)) * DIM + head * HDIM;
#pragma unroll
            for (int nt8 = 0; nt8 < 8; nt8++) {
                int n = nt8 * 8 + 2 * (lane & 3);
                float2 w; w.x = tf32r(oa[nt8][0] * invA); w.y = tf32r(oa[nt8][1] * invA);
                *(float2*)(dst + n) = w;
            }
        }
        if (rB < TOK) {
            float* dst = o + ((size_t)(win * TOK + rB)) * DIM + head * HDIM;
#pragma unroll
            for (int nt8 = 0; nt8 < 8; nt8++) {
                int n = nt8 * 8 + 2 * (lane & 3);
                float2 w; w.x = tf32r(oa[nt8][2] * invB); w.y = tf32r(oa[nt8][3] * invB);
                *(float2*)(dst + n) = w;
            }
        }
    }
}

// ---------------- launcher ----------------
extern "C" void kernel_launch(void* const* d_in, const int* in_sizes, int n_in,
                              void* d_out, int out_size) {
    const float* x     = (const float*)d_in[0];
    const float* n1g   = (const float*)d_in[1];
    const float* n1b   = (const float*)d_in[2];
    const float* qkvw  = (const float*)d_in[3];
    const float* qkvb  = (const float*)d_in[4];
    const float* projw = (const float*)d_in[5];
    const float* projb = (const float*)d_in[6];
    const float* rph   = (const float*)d_in[7];
    const float* rpw   = (const float*)d_in[8];
    const float* n2g   = (const float*)d_in[9];
    const float* n2b   = (const float*)d_in[10];
    const float* l1w   = (const float*)d_in[11];
    const float* l1b   = (const float*)d_in[12];
    const float* l2w   = (const float*)d_in[13];
    const float* l2b   = (const float*)d_in[14];
    float* out = (float*)d_out;

    cudaFuncSetAttribute(attn_k, cudaFuncAttributeMaxDynamicSharedMemorySize, AT_SMEM);
    cudaFuncSetAttribute(tgemm_k<0>, cudaFuncAttributeMaxDynamicSharedMemorySize, SMEM_GEMM);
    cudaFuncSetAttribute(tgemm_k<1>, cudaFuncAttributeMaxDynamicSharedMemorySize, SMEM_GEMM);
    cudaFuncSetAttribute(tgemm_k<2>, cudaFuncAttributeMaxDynamicSharedMemorySize, SMEM_GEMM);
    cudaFuncSetAttribute(tgemm_k<3>, cudaFuncAttributeMaxDynamicSharedMemorySize, SMEM_GEMM);

    float *p_a1, *p_qkv, *p_at, *p_hid, *p_a2, *p_h;
    float *p_wq, *p_wp, *p_w1, *p_w2;
    cudaGetSymbolAddress((void**)&p_a1,  g_a1);
    cudaGetSymbolAddress((void**)&p_qkv, g_qkv);
    cudaGetSymbolAddress((void**)&p_at,  g_at);
    cudaGetSymbolAddress((void**)&p_hid, g_hid);
    cudaGetSymbolAddress((void**)&p_a2,  g_a2);
    cudaGetSymbolAddress((void**)&p_h,   g_h);
    cudaGetSymbolAddress((void**)&p_wq,  g_wq);
    cudaGetSymbolAddress((void**)&p_wp,  g_wp);
    cudaGetSymbolAddress((void**)&p_w1,  g_w1);
    cudaGetSymbolAddress((void**)&p_w2,  g_w2);

    dim3 tb(32, 8);
    wprep_k<<<dim3(3 * DIM / 32, DIM / 32), tb>>>(qkvw,  p_wq, DIM,  3 * DIM);
    wprep_k<<<dim3(DIM / 32, DIM / 32),     tb>>>(projw, p_wp, DIM,  DIM);

    // 1) LN1 + window-partition -> tf32 plane
    ln_k<<<MROWS, 256>>>(x, n1g, n1b, p_a1, 1);

    // 2) QKV GEMM -> fp32 qkv   (50176 x 2304 x 768)
    tgemm_k<0><<<dim3(18, 392), 128, SMEM_GEMM>>>(p_a1, p_wq,
        qkvb, nullptr, p_qkv, nullptr, MROWS, 3 * DIM, DIM);

    // 3) fused MMA attention -> tf32 plane
    attn_k<<<dim3(NWIN, NHD), 128, AT_SMEM>>>(p_qkv, rph, rpw, p_at);

    // 4) proj GEMM + unpartition + residual -> g_hid (fp32)
    tgemm_k<2><<<dim3(6, 392), 128, SMEM_GEMM>>>(p_at, p_wp,
        projb, x, p_hid, nullptr, MROWS, DIM, DIM);

    // 5) LN2 -> tf32 plane
    ln_k<<<MROWS, 256>>>(p_hid, n2g, n2b, p_a2, 0);

    wprep_k<<<dim3(MLPD / 32, DIM / 32), tb>>>(l1w, p_w1, DIM, MLPD);

    // 6) MLP1 + gelu -> tf32 plane   (50176 x 3072 x 768)
    tgemm_k<1><<<dim3(24, 392), 128, SMEM_GEMM>>>(p_a2, p_w1,
        l1b, nullptr, nullptr, p_h, MROWS, MLPD, DIM);

    wprep_k<<<dim3(DIM / 32, MLPD / 32), tb>>>(l2w, p_w2, MLPD, DIM);

    // 7) MLP2 + residual -> out (fp32)   (50176 x 768 x 3072)
    tgemm_k<3><<<dim3(6, 392), 128, SMEM_GEMM>>>(p_h, p_w2,
        l2b, p_hid, out, nullptr, MROWS, DIM, MLPD);
}

// round 11
// speedup vs baseline: 2.2464x; 1.0499x over previous
#include <cuda_runtime.h>
#include <math.h>
#include <stdint.h>

// ---------------- problem constants ----------------
#define BQ    16
#define ISZ   56
#define DIM   768
#define NHD   12
#define HDIM  64
#define WSZ   14
#define TOK   196
#define NWIN  256
#define MROWS 50176
#define MLPD  3072

typedef unsigned long long ull;

// ---------------- scratch (device globals) ----------------
__device__ __align__(16) float g_a1 [(size_t)MROWS * DIM];
__device__ __align__(16) float g_qkv[(size_t)MROWS * 3 * DIM];
__device__ __align__(16) float g_at [(size_t)MROWS * DIM];
__device__ __align__(16) float g_hid[(size_t)MROWS * DIM];
__device__ __align__(16) float g_a2 [(size_t)MROWS * DIM];
__device__ __align__(16) float g_h  [(size_t)MROWS * MLPD];
// transposed tf32-rounded weights: T[n][k]
__device__ __align__(16) float g_wq[(size_t)(3 * DIM) * DIM];
__device__ __align__(16) float g_wp[(size_t)DIM * DIM];
__device__ __align__(16) float g_w1[(size_t)MLPD * DIM];
__device__ __align__(16) float g_w2[(size_t)DIM * MLPD];

// ---------------- helpers ----------------
__device__ __forceinline__ float tf32r(float x) {
    uint32_t u;
    asm("cvt.rna.tf32.f32 %0, %1;" : "=r"(u) : "f"(x));
    return __uint_as_float(u);
}
__device__ __forceinline__ uint32_t smem_u32(const void* p) {
    uint32_t a;
    asm("{ .reg .u64 t; cvta.to.shared.u64 t, %1; cvt.u32.u64 %0, t; }" : "=r"(a) : "l"(p));
    return a;
}

// f32x2 packed math
__device__ __forceinline__ ull pk2(float lo, float hi) {
    ull r; asm("mov.b64 %0, {%1, %2};" : "=l"(r) : "f"(lo), "f"(hi)); return r;
}
__device__ __forceinline__ float2 upk2(ull v) {
    float2 f; asm("mov.b64 {%0, %1}, %2;" : "=f"(f.x), "=f"(f.y) : "l"(v)); return f;
}
__device__ __forceinline__ void fma2(ull& c, ull a, ull b) {
    asm("fma.rn.f32x2 %0, %1, %2, %3;" : "=l"(c) : "l"(a), "l"(b), "l"(c));
}

// window-token row m -> flat pixel p
__device__ __forceinline__ int m_to_p(int m) {
    int win = m / TOK, tok = m - win * TOK;
    int b = win >> 4, wr = win & 15;
    int wh = wr >> 2, ww = wr & 3;
    int i = tok / WSZ, j = tok - i * WSZ;
    return (b * ISZ + wh * WSZ + i) * ISZ + ww * WSZ + j;
}

__device__ __forceinline__ int div14(int x) { return (x * 37450) >> 19; }   // valid x < 256

// ---------------- mma / ldmatrix / cp.async (base sm_80+ PTX) --------------
__device__ __forceinline__ void mma1688t(float* d, const uint32_t* a, const uint32_t* b) {
    asm volatile("mma.sync.aligned.m16n8k8.row.col.f32.tf32.tf32.f32 "
        "{%0,%1,%2,%3},{%4,%5,%6,%7},{%8,%9},{%0,%1,%2,%3};"
        : "+f"(d[0]), "+f"(d[1]), "+f"(d[2]), "+f"(d[3])
        : "r"(a[0]), "r"(a[1]), "r"(a[2]), "r"(a[3]), "r"(b[0]), "r"(b[1]));
}
__device__ __forceinline__ void ldx4(uint32_t* r, uint32_t addr) {
    asm volatile("ldmatrix.sync.aligned.m8n8.x4.shared.b16 {%0,%1,%2,%3}, [%4];"
        : "=r"(r[0]), "=r"(r[1]), "=r"(r[2]), "=r"(r[3]) : "r"(addr));
}
__device__ __forceinline__ void cpa16(uint32_t dst, const void* src) {
    asm volatile("cp.async.cg.shared.global [%0], [%1], 16;" :: "r"(dst), "l"(src));
}
#define CP_COMMIT() asm volatile("cp.async.commit_group;" ::: "memory")
#define CP_WAIT2()  asm volatile("cp.async.wait_group 2;" ::: "memory")

// ---------------- weight transpose -> tf32-rounded fp32 ----------------
__global__ void __launch_bounds__(256) wprep_k(const float* __restrict__ W,
                                               float* __restrict__ T,
                                               int K, int N) {
    __shared__ float t[32][33];
    int nb = blockIdx.x * 32, kb = blockIdx.y * 32;
    int tx = threadIdx.x, ty = threadIdx.y;
#pragma unroll
    for (int j = 0; j < 32; j += 8)
        t[ty + j][tx] = W[(size_t)(kb + ty + j) * N + nb + tx];
    __syncthreads();
#pragma unroll
    for (int j = 0; j < 32; j += 8)
        T[(size_t)(nb + ty + j) * K + kb + tx] = tf32r(t[tx][ty + j]);
}

// ---------------- LayerNorm (float4, 192 threads) -> tf32 plane ------------
__global__ void __launch_bounds__(192) ln_k(const float* __restrict__ in,
                                            const float* __restrict__ gg,
                                            const float* __restrict__ bb,
                                            float* __restrict__ o,
                                            int windowed) {
    int blk = blockIdx.x;
    int src = windowed ? m_to_p(blk) : blk;
    const float* xr = in + (size_t)src * DIM;
    int t = threadIdx.x;
    float4 v = *(const float4*)(xr + 4 * t);
    float s  = v.x + v.y + v.z + v.w;
    float sq = v.x * v.x + v.y * v.y + v.z * v.z + v.w * v.w;
#pragma unroll
    for (int off = 16; off > 0; off >>= 1) {
        s  += __shfl_xor_sync(0xffffffffu, s, off);
        sq += __shfl_xor_sync(0xffffffffu, sq, off);
    }
    __shared__ float sh[12];
    int wid = t >> 5, lane = t & 31;
    if (!lane) { sh[wid] = s; sh[6 + wid] = sq; }
    __syncthreads();
    float st = 0.f, sqt = 0.f;
#pragma unroll
    for (int i = 0; i < 6; i++) { st += sh[i]; sqt += sh[6 + i]; }
    float mu = st * (1.0f / 768.0f);
    float var = sqt * (1.0f / 768.0f) - mu * mu;
    float rstd = rsqrtf(var + 1e-5f);
    float4 g = *(const float4*)(gg + 4 * t);
    float4 b = *(const float4*)(bb + 4 * t);
    float4 w;
    w.x = tf32r((v.x - mu) * rstd * g.x + b.x);
    w.y = tf32r((v.y - mu) * rstd * g.y + b.y);
    w.z = tf32r((v.z - mu) * rstd * g.z + b.z);
    w.w = tf32r((v.w - mu) * rstd * g.w + b.w);
    *(float4*)(o + (size_t)blk * DIM + 4 * t) = w;
}

// ---------------- tf32 HMMA GEMM (unchanged from R8/R10) -------------------
#define ROWB 144
#define A_PL (128 * ROWB)
#define STAGE_BYTES (2 * A_PL)
#define SMEM_GEMM (3 * STAGE_BYTES + 256)

template <int EPI>
__global__ void __launch_bounds__(128, 2)
tgemm_k(const float* __restrict__ A, const float* __restrict__ B,
        const float* __restrict__ bias, const float* __restrict__ res,
        float* __restrict__ C, float* __restrict__ Cr,
        int M, int N, int K) {
    extern __shared__ char dyn[];
    uint32_t sb = (smem_u32(dyn) + 255) & ~255u;

    const int tid = threadIdx.x, lane = tid & 31, wid = tid >> 5;
    const int bm = blockIdx.y * 128, bn = blockIdx.x * 128;
    const int wm = (wid >> 1) * 64, wn = (wid & 1) * 64;
    const int nk = K >> 5;

    const float* gp[16]; uint32_t so[16];
#pragma unroll
    for (int q = 0; q < 16; q++) {
        int i = tid + q * 128;
        int isB = i >> 10, j = i & 1023, r = j >> 3, c = j & 7;
        gp[q] = (isB ? B + (size_t)(bn + r) * K : A + (size_t)(bm + r) * K) + c * 4;
        so[q] = (uint32_t)(isB * A_PL + r * ROWB + c * 16);
    }

    auto issue = [&](int stage, int t) {
        uint32_t s = sb + stage * STAGE_BYTES;
        int k0 = t * 32;
#pragma unroll
        for (int q = 0; q < 16; q++) cpa16(s + so[q], gp[q] + k0);
    };

    float acc[128];
#pragma unroll
    for (int i = 0; i < 128; i++) acc[i] = 0.f;

    const uint32_t aoff = (uint32_t)((((lane & 7) + ((lane >> 3) & 1) * 8) * ROWB) + (lane >> 4) * 16);
    const uint32_t boff = (uint32_t)((lane & 7) * ROWB + (lane >> 3) * 16);

    issue(0, 0); CP_COMMIT();
    issue(1, 1); CP_COMMIT();
    issue(2, 2); CP_COMMIT();

    for (int t = 0; t < nk; ++t) {
        CP_WAIT2();
        __syncthreads();

        uint32_t s = sb + (t % 3) * STAGE_BYTES;
#pragma unroll
        for (int sp = 0; sp < 2; sp++) {
            uint32_t af[2][4][4];
#pragma unroll
            for (int ks = 0; ks < 2; ks++)
#pragma unroll
                for (int mi = 0; mi < 4; mi++)
                    ldx4(af[ks][mi], s + (uint32_t)((wm + mi * 16) * ROWB) + (sp * 2 + ks) * 32 + aoff);
#pragma unroll
            for (int p = 0; p < 8; p++) {
                uint32_t bf[4];
                ldx4(bf, s + A_PL + (uint32_t)((wn + p * 8) * ROWB) + sp * 64 + boff);
#pragma unroll
                for (int mi = 0; mi < 4; mi++)
                    mma1688t(&acc[(mi * 8 + p) * 4], af[0][mi], bf);
#pragma unroll
                for (int mi = 0; mi < 4; mi++)
                    mma1688t(&acc[(mi * 8 + p) * 4], af[1][mi], bf + 2);
            }
        }

        __syncthreads();
        if (t + 3 < nk) issue(t % 3, t + 3);
        CP_COMMIT();
    }

#pragma unroll
    for (int mi = 0; mi < 4; mi++) {
        int r0 = bm + wm + mi * 16 + (lane >> 2);
#pragma unroll
        for (int p = 0; p < 8; p++) {
            int gn = bn + wn + p * 8 + (lane & 3) * 2;
            float* a = &acc[(mi * 8 + p) * 4];
            float b0 = bias[gn], b1 = bias[gn + 1];
#pragma unroll
            for (int h = 0; h < 2; h++) {
                int row = r0 + h * 8;
                float x0 = a[h * 2] + b0, x1 = a[h * 2 + 1] + b1;
                if (EPI == 1) {
                    float g0 = 0.5f * x0 * (1.0f + erff(x0 * 0.70710678118654752f));
                    float g1 = 0.5f * x1 * (1.0f + erff(x1 * 0.70710678118654752f));
                    float2 o; o.x = tf32r(g0); o.y = tf32r(g1);
                    *(float2*)(Cr + (size_t)row * N + gn) = o;
                } else if (EPI == 2) {
                    int pp = m_to_p(row);
                    const float* rp = res + (size_t)pp * DIM + gn;
                    float2 o; o.x = x0 + rp[0]; o.y = x1 + rp[1];
                    *(float2*)(C + (size_t)pp * DIM + gn) = o;
                } else if (EPI == 3) {
                    const float* rp = res + (size_t)row * N + gn;
                    float2 o; o.x = x0 + rp[0]; o.y = x1 + rp[1];
                    *(float2*)(C + (size_t)row * N + gn) = o;
                } else {
                    float2 o; o.x = x0; o.y = x1;
                    *(float2*)(C + (size_t)row * N + gn) = o;
                }
            }
        }
    }
}

// ---------------- fused tf32-MMA window attention (256 threads) ------------
// One CTA per (window, head). 8 warps.
#define AT_KROW 272
#define AT_VROW 848
#define AT_SM_K  0
#define AT_SM_V  (200 * AT_KROW)                   // 54400
#define AT_SM_T1 (AT_SM_V + 64 * AT_VROW)          // 108672
#define AT_SM_T2 (AT_SM_T1 + 208 * 28 * 4)         // 131968
#define AT_SM_Q  (AT_SM_T2 + 208 * 28 * 4)         // 155264
#define AT_SMEM  (AT_SM_Q + 8 * 16 * AT_KROW)      // 190080

// build m16k8 A-fragment of P from S-acc layout via quad shuffles
__device__ __forceinline__ void pfrag(const float* s4, uint32_t* a, int lane) {
    int j0 = lane & 3;
    int sA = (lane & ~3) | (j0 >> 1);
    float c0lo = __shfl_sync(0xffffffffu, s4[0], sA);
    float c1lo = __shfl_sync(0xffffffffu, s4[1], sA);
    float c2lo = __shfl_sync(0xffffffffu, s4[2], sA);
    float c3lo = __shfl_sync(0xffffffffu, s4[3], sA);
    float c0hi = __shfl_sync(0xffffffffu, s4[0], sA + 2);
    float c1hi = __shfl_sync(0xffffffffu, s4[1], sA + 2);
    float c2hi = __shfl_sync(0xffffffffu, s4[2], sA + 2);
    float c3hi = __shfl_sync(0xffffffffu, s4[3], sA + 2);
    bool odd = (j0 & 1) != 0;
    a[0] = __float_as_uint(odd ? c1lo : c0lo);
    a[1] = __float_as_uint(odd ? c3lo : c2lo);
    a[2] = __float_as_uint(odd ? c1hi : c0hi);
    a[3] = __float_as_uint(odd ? c3hi : c2hi);
}

__global__ void __launch_bounds__(256) attn_k(const float* __restrict__ qkv,
                                              const float* __restrict__ rph,
                                              const float* __restrict__ rpw,
                                              float* __restrict__ o) {
    extern __shared__ char sm[];
    uint32_t sb = smem_u32(sm);
    const int win = blockIdx.x, head = blockIdx.y;
    const int tid = threadIdx.x, lane = tid & 31, wid = tid >> 5;
    const float* base = qkv + (size_t)win * TOK * (3 * DIM) + head * HDIM;

    // ---- K (keys 0..199; pad rows zero), tf32-rounded ----
    for (int i = tid; i < 200 * 16; i += 256) {
        int r = i >> 4, c4 = (i & 15) << 2;
        float4 v = make_float4(0.f, 0.f, 0.f, 0.f);
        if (r < TOK) v = *(const float4*)(base + (size_t)r * (3 * DIM) + DIM + c4);
        float4 w; w.x = tf32r(v.x); w.y = tf32r(v.y); w.z = tf32r(v.z); w.w = tf32r(v.w);
        *(float4*)(sm + AT_SM_K + r * AT_KROW + c4 * 4) = w;
    }
    // ---- V transposed: V^T[dim][key] ----
    for (int r = tid; r < TOK; r += 256) {
        const float* src = base + (size_t)r * (3 * DIM) + 2 * DIM;
#pragma unroll
        for (int d4 = 0; d4 < HDIM; d4 += 4) {
            float4 v = *(const float4*)(src + d4);
            *(float*)(sm + AT_SM_V + (d4 + 0) * AT_VROW + r * 4) = tf32r(v.x);
            *(float*)(sm + AT_SM_V + (d4 + 1) * AT_VROW + r * 4) = tf32r(v.y);
            *(float*)(sm + AT_SM_V + (d4 + 2) * AT_VROW + r * 4) = tf32r(v.z);
            *(float*)(sm + AT_SM_V + (d4 + 3) * AT_VROW + r * 4) = tf32r(v.w);
        }
    }
    // zero V^T pad keys 196..199
    for (int i = tid; i < 64 * 4; i += 256) {
        int r = i >> 2, c = 196 + (i & 3);
        *(float*)(sm + AT_SM_V + r * AT_VROW + c * 4) = 0.f;
    }
    // ---- bias tables T1[q][idx] = q . rph[idx], T2 likewise ----
    for (int q = tid; q < 208; q += 256) {
        float* t1 = (float*)(sm + AT_SM_T1) + q * 28;
        float* t2 = (float*)(sm + AT_SM_T2) + q * 28;
        if (q < TOK) {
            ull qr[32];
#pragma unroll
            for (int d = 0; d < HDIM; d += 4) {
                float4 v = *(const float4*)(base + (size_t)q * (3 * DIM) + d);
                qr[d >> 1]       = pk2(v.x, v.y);
                qr[(d >> 1) + 1] = pk2(v.z, v.w);
            }
            for (int idx = 0; idx < 27; idx++) {
                const ull* r1 = (const ull*)(rph + (size_t)idx * HDIM);
                const ull* r2 = (const ull*)(rpw + (size_t)idx * HDIM);
                ull a0 = 0, a1 = 0, b0 = 0, b1 = 0;
#pragma unroll
                for (int j = 0; j < 32; j += 2) {
                    fma2(a0, qr[j], r1[j]); fma2(a1, qr[j + 1], r1[j + 1]);
                    fma2(b0, qr[j], r2[j]); fma2(b1, qr[j + 1], r2[j + 1]);
                }
                float2 fa0 = upk2(a0), fa1 = upk2(a1), fb0 = upk2(b0), fb1 = upk2(b1);
                t1[idx] = fa0.x + fa0.y + fa1.x + fa1.y;
                t2[idx] = fb0.x + fb0.y + fb1.x + fb1.y;
            }
        } else {
            for (int idx = 0; idx < 28; idx++) { t1[idx] = 0.f; t2[idx] = 0.f; }
        }
    }
    __syncthreads();

    const uint32_t aoff  = (uint32_t)((((lane & 7) + ((lane >> 3) & 1) * 8) * AT_KROW) + (lane >> 4) * 16);
    const uint32_t boffK = (uint32_t)((lane & 7) * AT_KROW + (lane >> 3) * 16);
    const uint32_t boffV = (uint32_t)((lane & 7) * AT_VROW + (lane >> 3) * 16);
    const uint32_t qstage = sb + AT_SM_Q + wid * 16 * AT_KROW;

    for (int mt = wid; mt < 13; mt += 8) {
        const int mrow0 = mt * 16;
        // stage Q tile (scaled, tf32-rounded; clamp pad rows)
        for (int i = lane; i < 16 * 16; i += 32) {
            int r = i >> 4, c4 = (i & 15) << 2;
            int gr = mrow0 + r; if (gr > TOK - 1) gr = TOK - 1;
            float4 v = *(const float4*)(base + (size_t)gr * (3 * DIM) + c4);
            float4 w; w.x = tf32r(v.x * 0.125f); w.y = tf32r(v.y * 0.125f);
            w.z = tf32r(v.z * 0.125f); w.w = tf32r(v.w * 0.125f);
            *(float4*)(sm + AT_SM_Q + wid * 16 * AT_KROW + r * AT_KROW + c4 * 4) = w;
        }
        __syncwarp();
        uint32_t qf[8][4];
#pragma unroll
        for (int ks = 0; ks < 8; ks++) ldx4(qf[ks], qstage + ks * 32 + aoff);

        // ---- S = Qs @ K^T (25 n-tiles); j covers dims 16j..16j+15 -> j*64 B ----
        float sc[25][4];
#pragma unroll
        for (int nt = 0; nt < 25; nt++) { sc[nt][0] = 0.f; sc[nt][1] = 0.f; sc[nt][2] = 0.f; sc[nt][3] = 0.f; }
#pragma unroll
        for (int j = 0; j < 4; j++) {
#pragma unroll
            for (int nt = 0; nt < 25; nt++) {
                uint32_t bf[4];
                ldx4(bf, sb + AT_SM_K + (uint32_t)(nt * 8 * AT_KROW) + j * 64 + boffK);
                mma1688t(sc[nt], qf[2 * j], bf);
                mma1688t(sc[nt], qf[2 * j + 1], bf + 2);
            }
        }

        // ---- bias + mask + softmax (exact, full row in regs) ----
        const int rA = mrow0 + (lane >> 2), rB = rA + 8;
        const int qiA = div14(rA), qjA = rA - qiA * 14;
        const int qiB = div14(rB), qjB = rB - qiB * 14;
        const float* T1A = (const float*)(sm + AT_SM_T1) + rA * 28 + qiA + 13;
        const float* T2A = (const float*)(sm + AT_SM_T2) + rA * 28 + qjA + 13;
        const float* T1B = (const float*)(sm + AT_SM_T1) + rB * 28 + qiB + 13;
        const float* T2B = (const float*)(sm + AT_SM_T2) + rB * 28 + qjB + 13;
        float mxA = -3e38f, mxB = -3e38f;
#pragma unroll
        for (int nt = 0; nt < 25; nt++) {
            int c0 = nt * 8 + 2 * (lane & 3), c1 = c0 + 1;
            int cc0 = c0 > 195 ? 195 : c0, cc1 = c1 > 195 ? 195 : c1;
            int kh0 = div14(cc0), kw0 = cc0 - kh0 * 14;
            int kh1 = div14(cc1), kw1 = cc1 - kh1 * 14;
            sc[nt][0] = (c0 < TOK) ? sc[nt][0] + T1A[-kh0] + T2A[-kw0] : -3e38f;
            sc[nt][1] = (c1 < TOK) ? sc[nt][1] + T1A[-kh1] + T2A[-kw1] : -3e38f;
            sc[nt][2] = (c0 < TOK) ? sc[nt][2] + T1B[-kh0] + T2B[-kw0] : -3e38f;
            sc[nt][3] = (c1 < TOK) ? sc[nt][3] + T1B[-kh1] + T2B[-kw1] : -3e38f;
            mxA = fmaxf(mxA, fmaxf(sc[nt][0], sc[nt][1]));
            mxB = fmaxf(mxB, fmaxf(sc[nt][2], sc[nt][3]));
        }
        mxA = fmaxf(mxA, __shfl_xor_sync(0xffffffffu, mxA, 1));
        mxA = fmaxf(mxA, __shfl_xor_sync(0xffffffffu, mxA, 2));
        mxB = fmaxf(mxB, __shfl_xor_sync(0xffffffffu, mxB, 1));
        mxB = fmaxf(mxB, __shfl_xor_sync(0xffffffffu, mxB, 2));
        float lA = 0.f, lB = 0.f;
#pragma unroll
        for (int nt = 0; nt < 25; nt++) {
            float p0 = __expf(sc[nt][0] - mxA);
            float p1 = __expf(sc[nt][1] - mxA);
            float p2 = __expf(sc[nt][2] - mxB);
            float p3 = __expf(sc[nt][3] - mxB);
            lA += p0 + p1; lB += p2 + p3;
            sc[nt][0] = tf32r(p0); sc[nt][1] = tf32r(p1);
            sc[nt][2] = tf32r(p2); sc[nt][3] = tf32r(p3);
        }
        lA += __shfl_xor_sync(0xffffffffu, lA, 1);
        lA += __shfl_xor_sync(0xffffffffu, lA, 2);
        lB += __shfl_xor_sync(0xffffffffu, lB, 1);
        lB += __shfl_xor_sync(0xffffffffu, lB, 2);

        // ---- O = P @ V (8 dim-tiles) ----
        float oa[8][4];
#pragma unroll
        for (int nt8 = 0; nt8 < 8; nt8++) { oa[nt8][0] = 0.f; oa[nt8][1] = 0.f; oa[nt8][2] = 0.f; oa[nt8][3] = 0.f; }
#pragma unroll
        for (int cp = 0; cp < 12; cp++) {
            uint32_t pa0[4], pa1[4];
            pfrag(sc[2 * cp], pa0, lane);
            pfrag(sc[2 * cp + 1], pa1, lane);
#pragma unroll
            for (int nt8 = 0; nt8 < 8; nt8++) {
                uint32_t bf[4];
                ldx4(bf, sb + AT_SM_V + (uint32_t)(nt8 * 8 * AT_VROW) + cp * 64 + boffV);
                mma1688t(oa[nt8], pa0, bf);
                mma1688t(oa[nt8], pa1, bf + 2);
            }
        }
        {   // tail chunk 24 (keys 192..199)
            uint32_t pa[4];
            pfrag(sc[24], pa, lane);
#pragma unroll
            for (int nt8 = 0; nt8 < 8; nt8++) {
                uint32_t bf[4];
                ldx4(bf, sb + AT_SM_V + (uint32_t)(nt8 * 8 * AT_VROW) + 12 * 64 + boffV);
                mma1688t(oa[nt8], pa, bf);
            }
        }

        // ---- normalize + store ----
        float invA = 1.f / lA, invB = 1.f / lB;
        if (rA < TOK) {
            float* dst = o + ((size_t)(win * TOK + rA)) * DIM + head * HDIM;
#pragma unroll
            for (int nt8 = 0; nt8 < 8; nt8++) {
                int n = nt8 * 8 + 2 * (lane & 3);
                float2 w; w.x = tf32r(oa[nt8][0] * invA); w.y = tf32r(oa[nt8][1] * invA);
                *(float2*)(dst + n) = w;
            }
        }
        if (rB < TOK) {
            float* dst = o + ((size_t)(win * TOK + rB)) * DIM + head * HDIM;
#pragma unroll
            for (int nt8 = 0; nt8 < 8; nt8++) {
                int n = nt8 * 8 + 2 * (lane & 3);
                float2 w; w.x = tf32r(oa[nt8][2] * invB); w.y = tf32r(oa[nt8][3] * invB);
                *(float2*)(dst + n) = w;
            }
        }
    }
}

// ---------------- launcher ----------------
extern "C" void kernel_launch(void* const* d_in, const int* in_sizes, int n_in,
                              void* d_out, int out_size) {
    const float* x     = (const float*)d_in[0];
    const float* n1g   = (const float*)d_in[1];
    const float* n1b   = (const float*)d_in[2];
    const float* qkvw  = (const float*)d_in[3];
    const float* qkvb  = (const float*)d_in[4];
    const float* projw = (const float*)d_in[5];
    const float* projb = (const float*)d_in[6];
    const float* rph   = (const float*)d_in[7];
    const float* rpw   = (const float*)d_in[8];
    const float* n2g   = (const float*)d_in[9];
    const float* n2b   = (const float*)d_in[10];
    const float* l1w   = (const float*)d_in[11];
    const float* l1b   = (const float*)d_in[12];
    const float* l2w   = (const float*)d_in[13];
    const float* l2b   = (const float*)d_in[14];
    float* out = (float*)d_out;

    cudaFuncSetAttribute(attn_k, cudaFuncAttributeMaxDynamicSharedMemorySize, AT_SMEM);
    cudaFuncSetAttribute(tgemm_k<0>, cudaFuncAttributeMaxDynamicSharedMemorySize, SMEM_GEMM);
    cudaFuncSetAttribute(tgemm_k<1>, cudaFuncAttributeMaxDynamicSharedMemorySize, SMEM_GEMM);
    cudaFuncSetAttribute(tgemm_k<2>, cudaFuncAttributeMaxDynamicSharedMemorySize, SMEM_GEMM);
    cudaFuncSetAttribute(tgemm_k<3>, cudaFuncAttributeMaxDynamicSharedMemorySize, SMEM_GEMM);

    float *p_a1, *p_qkv, *p_at, *p_hid, *p_a2, *p_h;
    float *p_wq, *p_wp, *p_w1, *p_w2;
    cudaGetSymbolAddress((void**)&p_a1,  g_a1);
    cudaGetSymbolAddress((void**)&p_qkv, g_qkv);
    cudaGetSymbolAddress((void**)&p_at,  g_at);
    cudaGetSymbolAddress((void**)&p_hid, g_hid);
    cudaGetSymbolAddress((void**)&p_a2,  g_a2);
    cudaGetSymbolAddress((void**)&p_h,   g_h);
    cudaGetSymbolAddress((void**)&p_wq,  g_wq);
    cudaGetSymbolAddress((void**)&p_wp,  g_wp);
    cudaGetSymbolAddress((void**)&p_w1,  g_w1);
    cudaGetSymbolAddress((void**)&p_w2,  g_w2);

    dim3 tb(32, 8);
    wprep_k<<<dim3(3 * DIM / 32, DIM / 32), tb>>>(qkvw,  p_wq, DIM,  3 * DIM);
    wprep_k<<<dim3(DIM / 32, DIM / 32),     tb>>>(projw, p_wp, DIM,  DIM);

    // 1) LN1 + window-partition -> tf32 plane
    ln_k<<<MROWS, 192>>>(x, n1g, n1b, p_a1, 1);

    // 2) QKV GEMM -> fp32 qkv   (50176 x 2304 x 768)
    tgemm_k<0><<<dim3(18, 392), 128, SMEM_GEMM>>>(p_a1, p_wq,
        qkvb, nullptr, p_qkv, nullptr, MROWS, 3 * DIM, DIM);

    // 3) fused MMA attention -> tf32 plane
    attn_k<<<dim3(NWIN, NHD), 256, AT_SMEM>>>(p_qkv, rph, rpw, p_at);

    // 4) proj GEMM + unpartition + residual -> g_hid (fp32)
    tgemm_k<2><<<dim3(6, 392), 128, SMEM_GEMM>>>(p_at, p_wp,
        projb, x, p_hid, nullptr, MROWS, DIM, DIM);

    // 5) LN2 -> tf32 plane
    ln_k<<<MROWS, 192>>>(p_hid, n2g, n2b, p_a2, 0);

    wprep_k<<<dim3(MLPD / 32, DIM / 32), tb>>>(l1w, p_w1, DIM, MLPD);

    // 6) MLP1 + gelu -> tf32 plane   (50176 x 3072 x 768)
    tgemm_k<1><<<dim3(24, 392), 128, SMEM_GEMM>>>(p_a2, p_w1,
        l1b, nullptr, nullptr, p_h, MROWS, MLPD, DIM);

    wprep_k<<<dim3(DIM / 32, MLPD / 32), tb>>>(l2w, p_w2, MLPD, DIM);

    // 7) MLP2 + residual -> out (fp32)   (50176 x 768 x 3072)
    tgemm_k<3><<<dim3(6, 392), 128, SMEM_GEMM>>>(p_h, p_w2,
        l2b, p_hid, out, nullptr, MROWS, DIM, MLPD);
}

// round 12
// speedup vs baseline: 2.2535x; 1.0032x over previous
#include <cuda_runtime.h>
#include <math.h>
#include <stdint.h>

// ---------------- problem constants ----------------
#define BQ    16
#define ISZ   56
#define DIM   768
#define NHD   12
#define HDIM  64
#define WSZ   14
#define TOK   196
#define NWIN  256
#define MROWS 50176
#define MLPD  3072

typedef unsigned long long ull;

// ---------------- scratch (device globals) ----------------
__device__ __align__(16) float g_a1 [(size_t)MROWS * DIM];
__device__ __align__(16) float g_qkv[(size_t)MROWS * 3 * DIM];
__device__ __align__(16) float g_at [(size_t)MROWS * DIM];
__device__ __align__(16) float g_hid[(size_t)MROWS * DIM];
__device__ __align__(16) float g_a2 [(size_t)MROWS * DIM];
__device__ __align__(16) float g_h  [(size_t)MROWS * MLPD];
// transposed tf32-rounded weights: T[n][k]
__device__ __align__(16) float g_wq[(size_t)(3 * DIM) * DIM];
__device__ __align__(16) float g_wp[(size_t)DIM * DIM];
__device__ __align__(16) float g_w1[(size_t)MLPD * DIM];
__device__ __align__(16) float g_w2[(size_t)DIM * MLPD];

// ---------------- helpers ----------------
__device__ __forceinline__ float tf32r(float x) {
    uint32_t u;
    asm("cvt.rna.tf32.f32 %0, %1;" : "=r"(u) : "f"(x));
    return __uint_as_float(u);
}
__device__ __forceinline__ uint32_t smem_u32(const void* p) {
    uint32_t a;
    asm("{ .reg .u64 t; cvta.to.shared.u64 t, %1; cvt.u32.u64 %0, t; }" : "=r"(a) : "l"(p));
    return a;
}

// f32x2 packed math
__device__ __forceinline__ ull pk2(float lo, float hi) {
    ull r; asm("mov.b64 %0, {%1, %2};" : "=l"(r) : "f"(lo), "f"(hi)); return r;
}
__device__ __forceinline__ float2 upk2(ull v) {
    float2 f; asm("mov.b64 {%0, %1}, %2;" : "=f"(f.x), "=f"(f.y) : "l"(v)); return f;
}
__device__ __forceinline__ void fma2(ull& c, ull a, ull b) {
    asm("fma.rn.f32x2 %0, %1, %2, %3;" : "=l"(c) : "l"(a), "l"(b), "l"(c));
}

// window-token row m -> flat pixel p
__device__ __forceinline__ int m_to_p(int m) {
    int win = m / TOK, tok = m - win * TOK;
    int b = win >> 4, wr = win & 15;
    int wh = wr >> 2, ww = wr & 3;
    int i = tok / WSZ, j = tok - i * WSZ;
    return (b * ISZ + wh * WSZ + i) * ISZ + ww * WSZ + j;
}

__device__ __forceinline__ int div14(int x) { return (x * 37450) >> 19; }   // valid x < 256

// ---------------- mma / ldmatrix / cp.async (base sm_80+ PTX) --------------
__device__ __forceinline__ void mma1688t(float* d, const uint32_t* a, const uint32_t* b) {
    asm volatile("mma.sync.aligned.m16n8k8.row.col.f32.tf32.tf32.f32 "
        "{%0,%1,%2,%3},{%4,%5,%6,%7},{%8,%9},{%0,%1,%2,%3};"
        : "+f"(d[0]), "+f"(d[1]), "+f"(d[2]), "+f"(d[3])
        : "r"(a[0]), "r"(a[1]), "r"(a[2]), "r"(a[3]), "r"(b[0]), "r"(b[1]));
}
__device__ __forceinline__ void ldx4(uint32_t* r, uint32_t addr) {
    asm volatile("ldmatrix.sync.aligned.m8n8.x4.shared.b16 {%0,%1,%2,%3}, [%4];"
        : "=r"(r[0]), "=r"(r[1]), "=r"(r[2]), "=r"(r[3]) : "r"(addr));
}
__device__ __forceinline__ void cpa16(uint32_t dst, const void* src) {
    asm volatile("cp.async.cg.shared.global [%0], [%1], 16;" :: "r"(dst), "l"(src));
}
#define CP_COMMIT() asm volatile("cp.async.commit_group;" ::: "memory")
#define CP_WAIT1()  asm volatile("cp.async.wait_group 1;" ::: "memory")

// ---------------- weight transpose -> tf32-rounded fp32 ----------------
__global__ void __launch_bounds__(256) wprep_k(const float* __restrict__ W,
                                               float* __restrict__ T,
                                               int K, int N) {
    __shared__ float t[32][33];
    int nb = blockIdx.x * 32, kb = blockIdx.y * 32;
    int tx = threadIdx.x, ty = threadIdx.y;
#pragma unroll
    for (int j = 0; j < 32; j += 8)
        t[ty + j][tx] = W[(size_t)(kb + ty + j) * N + nb + tx];
    __syncthreads();
#pragma unroll
    for (int j = 0; j < 32; j += 8)
        T[(size_t)(nb + ty + j) * K + kb + tx] = tf32r(t[tx][ty + j]);
}

// ---------------- LayerNorm (float4, 192 threads) -> tf32 plane ------------
__global__ void __launch_bounds__(192) ln_k(const float* __restrict__ in,
                                            const float* __restrict__ gg,
                                            const float* __restrict__ bb,
                                            float* __restrict__ o,
                                            int windowed) {
    int blk = blockIdx.x;
    int src = windowed ? m_to_p(blk) : blk;
    const float* xr = in + (size_t)src * DIM;
    int t = threadIdx.x;
    float4 v = *(const float4*)(xr + 4 * t);
    float s  = v.x + v.y + v.z + v.w;
    float sq = v.x * v.x + v.y * v.y + v.z * v.z + v.w * v.w;
#pragma unroll
    for (int off = 16; off > 0; off >>= 1) {
        s  += __shfl_xor_sync(0xffffffffu, s, off);
        sq += __shfl_xor_sync(0xffffffffu, sq, off);
    }
    __shared__ float sh[12];
    int wid = t >> 5, lane = t & 31;
    if (!lane) { sh[wid] = s; sh[6 + wid] = sq; }
    __syncthreads();
    float st = 0.f, sqt = 0.f;
#pragma unroll
    for (int i = 0; i < 6; i++) { st += sh[i]; sqt += sh[6 + i]; }
    float mu = st * (1.0f / 768.0f);
    float var = sqt * (1.0f / 768.0f) - mu * mu;
    float rstd = rsqrtf(var + 1e-5f);
    float4 g = *(const float4*)(gg + 4 * t);
    float4 b = *(const float4*)(bb + 4 * t);
    float4 w;
    w.x = tf32r((v.x - mu) * rstd * g.x + b.x);
    w.y = tf32r((v.y - mu) * rstd * g.y + b.y);
    w.z = tf32r((v.z - mu) * rstd * g.z + b.z);
    w.w = tf32r((v.w - mu) * rstd * g.w + b.w);
    *(float4*)(o + (size_t)blk * DIM + 4 * t) = w;
}

// ---------------- tf32 HMMA GEMM: single-sync early-issue pipeline ---------
// CTA 128x128, 4 warps of 64x64, k-chunk 32, 3-stage cp.async, 2 CTAs/SM.
// One barrier per k-iteration; stage t+2 issued into slot freed at iter t-1.
#define ROWB 144
#define A_PL (128 * ROWB)
#define STAGE_BYTES (2 * A_PL)
#define SMEM_GEMM (3 * STAGE_BYTES + 256)

template <int EPI>
__global__ void __launch_bounds__(128, 2)
tgemm_k(const float* __restrict__ A, const float* __restrict__ B,
        const float* __restrict__ bias, const float* __restrict__ res,
        float* __restrict__ C, float* __restrict__ Cr,
        int M, int N, int K) {
    extern __shared__ char dyn[];
    uint32_t sb = (smem_u32(dyn) + 255) & ~255u;

    const int tid = threadIdx.x, lane = tid & 31, wid = tid >> 5;
    const int bm = blockIdx.y * 128, bn = blockIdx.x * 128;
    const int wm = (wid >> 1) * 64, wn = (wid & 1) * 64;
    const int nk = K >> 5;

    const float* gp[16]; uint32_t so[16];
#pragma unroll
    for (int q = 0; q < 16; q++) {
        int i = tid + q * 128;
        int isB = i >> 10, j = i & 1023, r = j >> 3, c = j & 7;
        gp[q] = (isB ? B + (size_t)(bn + r) * K : A + (size_t)(bm + r) * K) + c * 4;
        so[q] = (uint32_t)(isB * A_PL + r * ROWB + c * 16);
    }

    auto issue = [&](int stage, int t) {
        uint32_t s = sb + stage * STAGE_BYTES;
        int k0 = t * 32;
#pragma unroll
        for (int q = 0; q < 16; q++) cpa16(s + so[q], gp[q] + k0);
    };

    float acc[128];
#pragma unroll
    for (int i = 0; i < 128; i++) acc[i] = 0.f;

    const uint32_t aoff = (uint32_t)((((lane & 7) + ((lane >> 3) & 1) * 8) * ROWB) + (lane >> 4) * 16);
    const uint32_t boff = (uint32_t)((lane & 7) * ROWB + (lane >> 3) * 16);

    issue(0, 0); CP_COMMIT();
    issue(1, 1); CP_COMMIT();

    for (int t = 0; t < nk; ++t) {
        CP_WAIT1();          // commits outstanding: 0..t+1 -> stage t landed
        __syncthreads();     // all warps done consuming iter t-1 (slot (t+2)%3 free)
        if (t + 2 < nk) issue((t + 2) % 3, t + 2);
        CP_COMMIT();         // unconditional: keeps group indexing consistent

        uint32_t s = sb + (t % 3) * STAGE_BYTES;
#pragma unroll
        for (int sp = 0; sp < 2; sp++) {
            uint32_t af[2][4][4];
#pragma unroll
            for (int ks = 0; ks < 2; ks++)
#pragma unroll
                for (int mi = 0; mi < 4; mi++)
                    ldx4(af[ks][mi], s + (uint32_t)((wm + mi * 16) * ROWB) + (sp * 2 + ks) * 32 + aoff);
#pragma unroll
            for (int p = 0; p < 8; p++) {
                uint32_t bf[4];
                ldx4(bf, s + A_PL + (uint32_t)((wn + p * 8) * ROWB) + sp * 64 + boff);
#pragma unroll
                for (int mi = 0; mi < 4; mi++)
                    mma1688t(&acc[(mi * 8 + p) * 4], af[0][mi], bf);
#pragma unroll
                for (int mi = 0; mi < 4; mi++)
                    mma1688t(&acc[(mi * 8 + p) * 4], af[1][mi], bf + 2);
            }
        }
    }

#pragma unroll
    for (int mi = 0; mi < 4; mi++) {
        int r0 = bm + wm + mi * 16 + (lane >> 2);
#pragma unroll
        for (int p = 0; p < 8; p++) {
            int gn = bn + wn + p * 8 + (lane & 3) * 2;
            float* a = &acc[(mi * 8 + p) * 4];
            float b0 = bias[gn], b1 = bias[gn + 1];
#pragma unroll
            for (int h = 0; h < 2; h++) {
                int row = r0 + h * 8;
                float x0 = a[h * 2] + b0, x1 = a[h * 2 + 1] + b1;
                if (EPI == 1) {
                    float g0 = 0.5f * x0 * (1.0f + erff(x0 * 0.70710678118654752f));
                    float g1 = 0.5f * x1 * (1.0f + erff(x1 * 0.70710678118654752f));
                    float2 o; o.x = tf32r(g0); o.y = tf32r(g1);
                    *(float2*)(Cr + (size_t)row * N + gn) = o;
                } else if (EPI == 2) {
                    int pp = m_to_p(row);
                    const float* rp = res + (size_t)pp * DIM + gn;
                    float2 o; o.x = x0 + rp[0]; o.y = x1 + rp[1];
                    *(float2*)(C + (size_t)pp * DIM + gn) = o;
                } else if (EPI == 3) {
                    const float* rp = res + (size_t)row * N + gn;
                    float2 o; o.x = x0 + rp[0]; o.y = x1 + rp[1];
                    *(float2*)(C + (size_t)row * N + gn) = o;
                } else {
                    float2 o; o.x = x0; o.y = x1;
                    *(float2*)(C + (size_t)row * N + gn) = o;
                }
            }
        }
    }
}

// ---------------- fused tf32-MMA window attention (256 threads) ------------
#define AT_KROW 272
#define AT_VROW 848
#define AT_SM_K  0
#define AT_SM_V  (200 * AT_KROW)                   // 54400
#define AT_SM_T1 (AT_SM_V + 64 * AT_VROW)          // 108672
#define AT_SM_T2 (AT_SM_T1 + 208 * 28 * 4)         // 131968
#define AT_SM_Q  (AT_SM_T2 + 208 * 28 * 4)         // 155264
#define AT_SMEM  (AT_SM_Q + 8 * 16 * AT_KROW)      // 190080

// build m16k8 A-fragment of P from S-acc layout via quad shuffles
__device__ __forceinline__ void pfrag(const float* s4, uint32_t* a, int lane) {
    int j0 = lane & 3;
    int sA = (lane & ~3) | (j0 >> 1);
    float c0lo = __shfl_sync(0xffffffffu, s4[0], sA);
    float c1lo = __shfl_sync(0xffffffffu, s4[1], sA);
    float c2lo = __shfl_sync(0xffffffffu, s4[2], sA);
    float c3lo = __shfl_sync(0xffffffffu, s4[3], sA);
    float c0hi = __shfl_sync(0xffffffffu, s4[0], sA + 2);
    float c1hi = __shfl_sync(0xffffffffu, s4[1], sA + 2);
    float c2hi = __shfl_sync(0xffffffffu, s4[2], sA + 2);
    float c3hi = __shfl_sync(0xffffffffu, s4[3], sA + 2);
    bool odd = (j0 & 1) != 0;
    a[0] = __float_as_uint(odd ? c1lo : c0lo);
    a[1] = __float_as_uint(odd ? c3lo : c2lo);
    a[2] = __float_as_uint(odd ? c1hi : c0hi);
    a[3] = __float_as_uint(odd ? c3hi : c2hi);
}

__global__ void __launch_bounds__(256) attn_k(const float* __restrict__ qkv,
                                              const float* __restrict__ rph,
                                              const float* __restrict__ rpw,
                                              float* __restrict__ o) {
    extern __shared__ char sm[];
    uint32_t sb = smem_u32(sm);
    const int win = blockIdx.x, head = blockIdx.y;
    const int tid = threadIdx.x, lane = tid & 31, wid = tid >> 5;
    const float* base = qkv + (size_t)win * TOK * (3 * DIM) + head * HDIM;

    // ---- K (keys 0..199; pad rows zero), tf32-rounded ----
    for (int i = tid; i < 200 * 16; i += 256) {
        int r = i >> 4, c4 = (i & 15) << 2;
        float4 v = make_float4(0.f, 0.f, 0.f, 0.f);
        if (r < TOK) v = *(const float4*)(base + (size_t)r * (3 * DIM) + DIM + c4);
        float4 w; w.x = tf32r(v.x); w.y = tf32r(v.y); w.z = tf32r(v.z); w.w = tf32r(v.w);
        *(float4*)(sm + AT_SM_K + r * AT_KROW + c4 * 4) = w;
    }
    // ---- V transposed: V^T[dim][key] ----
    for (int r = tid; r < TOK; r += 256) {
        const float* src = base + (size_t)r * (3 * DIM) + 2 * DIM;
#pragma unroll
        for (int d4 = 0; d4 < HDIM; d4 += 4) {
            float4 v = *(const float4*)(src + d4);
            *(float*)(sm + AT_SM_V + (d4 + 0) * AT_VROW + r * 4) = tf32r(v.x);
            *(float*)(sm + AT_SM_V + (d4 + 1) * AT_VROW + r * 4) = tf32r(v.y);
            *(float*)(sm + AT_SM_V + (d4 + 2) * AT_VROW + r * 4) = tf32r(v.z);
            *(float*)(sm + AT_SM_V + (d4 + 3) * AT_VROW + r * 4) = tf32r(v.w);
        }
    }
    // zero V^T pad keys 196..199
    for (int i = tid; i < 64 * 4; i += 256) {
        int r = i >> 2, c = 196 + (i & 3);
        *(float*)(sm + AT_SM_V + r * AT_VROW + c * 4) = 0.f;
    }
    // ---- bias tables T1[q][idx] = q . rph[idx], T2 likewise ----
    for (int q = tid; q < 208; q += 256) {
        float* t1 = (float*)(sm + AT_SM_T1) + q * 28;
        float* t2 = (float*)(sm + AT_SM_T2) + q * 28;
        if (q < TOK) {
            ull qr[32];
#pragma unroll
            for (int d = 0; d < HDIM; d += 4) {
                float4 v = *(const float4*)(base + (size_t)q * (3 * DIM) + d);
                qr[d >> 1]       = pk2(v.x, v.y);
                qr[(d >> 1) + 1] = pk2(v.z, v.w);
            }
            for (int idx = 0; idx < 27; idx++) {
                const ull* r1 = (const ull*)(rph + (size_t)idx * HDIM);
                const ull* r2 = (const ull*)(rpw + (size_t)idx * HDIM);
                ull a0 = 0, a1 = 0, b0 = 0, b1 = 0;
#pragma unroll
                for (int j = 0; j < 32; j += 2) {
                    fma2(a0, qr[j], r1[j]); fma2(a1, qr[j + 1], r1[j + 1]);
                    fma2(b0, qr[j], r2[j]); fma2(b1, qr[j + 1], r2[j + 1]);
                }
                float2 fa0 = upk2(a0), fa1 = upk2(a1), fb0 = upk2(b0), fb1 = upk2(b1);
                t1[idx] = fa0.x + fa0.y + fa1.x + fa1.y;
                t2[idx] = fb0.x + fb0.y + fb1.x + fb1.y;
            }
        } else {
            for (int idx = 0; idx < 28; idx++) { t1[idx] = 0.f; t2[idx] = 0.f; }
        }
    }
    __syncthreads();

    const uint32_t aoff  = (uint32_t)((((lane & 7) + ((lane >> 3) & 1) * 8) * AT_KROW) + (lane >> 4) * 16);
    const uint32_t boffK = (uint32_t)((lane & 7) * AT_KROW + (lane >> 3) * 16);
    const uint32_t boffV = (uint32_t)((lane & 7) * AT_VROW + (lane >> 3) * 16);
    const uint32_t qstage = sb + AT_SM_Q + wid * 16 * AT_KROW;

    for (int mt = wid; mt < 13; mt += 8) {
        const int mrow0 = mt * 16;
        // stage Q tile (scaled, tf32-rounded; clamp pad rows)
        for (int i = lane; i < 16 * 16; i += 32) {
            int r = i >> 4, c4 = (i & 15) << 2;
            int gr = mrow0 + r; if (gr > TOK - 1) gr = TOK - 1;
            float4 v = *(const float4*)(base + (size_t)gr * (3 * DIM) + c4);
            float4 w; w.x = tf32r(v.x * 0.125f); w.y = tf32r(v.y * 0.125f);
            w.z = tf32r(v.z * 0.125f); w.w = tf32r(v.w * 0.125f);
            *(float4*)(sm + AT_SM_Q + wid * 16 * AT_KROW + r * AT_KROW + c4 * 4) = w;
        }
        __syncwarp();
        uint32_t qf[8][4];
#pragma unroll
        for (int ks = 0; ks < 8; ks++) ldx4(qf[ks], qstage + ks * 32 + aoff);

        // ---- S = Qs @ K^T (25 n-tiles); j covers dims 16j..16j+15 -> j*64 B ----
        float sc[25][4];
#pragma unroll
        for (int nt = 0; nt < 25; nt++) { sc[nt][0] = 0.f; sc[nt][1] = 0.f; sc[nt][2] = 0.f; sc[nt][3] = 0.f; }
#pragma unroll
        for (int j = 0; j < 4; j++) {
#pragma unroll
            for (int nt = 0; nt < 25; nt++) {
                uint32_t bf[4];
                ldx4(bf, sb + AT_SM_K + (uint32_t)(nt * 8 * AT_KROW) + j * 64 + boffK);
                mma1688t(sc[nt], qf[2 * j], bf);
                mma1688t(sc[nt], qf[2 * j + 1], bf + 2);
            }
        }

        // ---- bias + mask + softmax (exact, full row in regs) ----
        const int rA = mrow0 + (lane >> 2), rB = rA + 8;
        const int qiA = div14(rA), qjA = rA - qiA * 14;
        const int qiB = div14(rB), qjB = rB - qiB * 14;
        const float* T1A = (const float*)(sm + AT_SM_T1) + rA * 28 + qiA + 13;
        const float* T2A = (const float*)(sm + AT_SM_T2) + rA * 28 + qjA + 13;
        const float* T1B = (const float*)(sm + AT_SM_T1) + rB * 28 + qiB + 13;
        const float* T2B = (const float*)(sm + AT_SM_T2) + rB * 28 + qjB + 13;
        float mxA = -3e38f, mxB = -3e38f;
#pragma unroll
        for (int nt = 0; nt < 25; nt++) {
            int c0 = nt * 8 + 2 * (lane & 3), c1 = c0 + 1;
            int cc0 = c0 > 195 ? 195 : c0, cc1 = c1 > 195 ? 195 : c1;
            int kh0 = div14(cc0), kw0 = cc0 - kh0 * 14;
            int kh1 = div14(cc1), kw1 = cc1 - kh1 * 14;
            sc[nt][0] = (c0 < TOK) ? sc[nt][0] + T1A[-kh0] + T2A[-kw0] : -3e38f;
            sc[nt][1] = (c1 < TOK) ? sc[nt][1] + T1A[-kh1] + T2A[-kw1] : -3e38f;
            sc[nt][2] = (c0 < TOK) ? sc[nt][2] + T1B[-kh0] + T2B[-kw0] : -3e38f;
            sc[nt][3] = (c1 < TOK) ? sc[nt][3] + T1B[-kh1] + T2B[-kw1] : -3e38f;
            mxA = fmaxf(mxA, fmaxf(sc[nt][0], sc[nt][1]));
            mxB = fmaxf(mxB, fmaxf(sc[nt][2], sc[nt][3]));
        }
        mxA = fmaxf(mxA, __shfl_xor_sync(0xffffffffu, mxA, 1));
        mxA = fmaxf(mxA, __shfl_xor_sync(0xffffffffu, mxA, 2));
        mxB = fmaxf(mxB, __shfl_xor_sync(0xffffffffu, mxB, 1));
        mxB = fmaxf(mxB, __shfl_xor_sync(0xffffffffu, mxB, 2));
        float lA = 0.f, lB = 0.f;
#pragma unroll
        for (int nt = 0; nt < 25; nt++) {
            float p0 = __expf(sc[nt][0] - mxA);
            float p1 = __expf(sc[nt][1] - mxA);
            float p2 = __expf(sc[nt][2] - mxB);
            float p3 = __expf(sc[nt][3] - mxB);
            lA += p0 + p1; lB += p2 + p3;
            sc[nt][0] = tf32r(p0); sc[nt][1] = tf32r(p1);
            sc[nt][2] = tf32r(p2); sc[nt][3] = tf32r(p3);
        }
        lA += __shfl_xor_sync(0xffffffffu, lA, 1);
        lA += __shfl_xor_sync(0xffffffffu, lA, 2);
        lB += __shfl_xor_sync(0xffffffffu, lB, 1);
        lB += __shfl_xor_sync(0xffffffffu, lB, 2);

        // ---- O = P @ V (8 dim-tiles) ----
        float oa[8][4];
#pragma unroll
        for (int nt8 = 0; nt8 < 8; nt8++) { oa[nt8][0] = 0.f; oa[nt8][1] = 0.f; oa[nt8][2] = 0.f; oa[nt8][3] = 0.f; }
#pragma unroll
        for (int cp = 0; cp < 12; cp++) {
            uint32_t pa0[4], pa1[4];
            pfrag(sc[2 * cp], pa0, lane);
            pfrag(sc[2 * cp + 1], pa1, lane);
#pragma unroll
            for (int nt8 = 0; nt8 < 8; nt8++) {
                uint32_t bf[4];
                ldx4(bf, sb + AT_SM_V + (uint32_t)(nt8 * 8 * AT_VROW) + cp * 64 + boffV);
                mma1688t(oa[nt8], pa0, bf);
                mma1688t(oa[nt8], pa1, bf + 2);
            }
        }
        {   // tail chunk 24 (keys 192..199)
            uint32_t pa[4];
            pfrag(sc[24], pa, lane);
#pragma unroll
            for (int nt8 = 0; nt8 < 8; nt8++) {
                uint32_t bf[4];
                ldx4(bf, sb + AT_SM_V + (uint32_t)(nt8 * 8 * AT_VROW) + 12 * 64 + boffV);
                mma1688t(oa[nt8], pa, bf);
            }
        }

        // ---- normalize + store ----
        float invA = 1.f / lA, invB = 1.f / lB;
        if (rA < TOK) {
            float* dst = o + ((size_t)(win * TOK + rA)) * DIM + head * HDIM;
#pragma unroll
            for (int nt8 = 0; nt8 < 8; nt8++) {
                int n = nt8 * 8 + 2 * (lane & 3);
                float2 w; w.x = tf32r(oa[nt8][0] * invA); w.y = tf32r(oa[nt8][1] * invA);
                *(float2*)(dst + n) = w;
            }
        }
        if (rB < TOK) {
            float* dst = o + ((size_t)(win * TOK + rB)) * DIM + head * HDIM;
#pragma unroll
            for (int nt8 = 0; nt8 < 8; nt8++) {
                int n = nt8 * 8 + 2 * (lane & 3);
                float2 w; w.x = tf32r(oa[nt8][2] * invB); w.y = tf32r(oa[nt8][3] * invB);
                *(float2*)(dst + n) = w;
            }
        }
    }
}

// ---------------- launcher ----------------
extern "C" void kernel_launch(void* const* d_in, const int* in_sizes, int n_in,
                              void* d_out, int out_size) {
    const float* x     = (const float*)d_in[0];
    const float* n1g   = (const float*)d_in[1];
    const float* n1b   = (const float*)d_in[2];
    const float* qkvw  = (const float*)d_in[3];
    const float* qkvb  = (const float*)d_in[4];
    const float* projw = (const float*)d_in[5];
    const float* projb = (const float*)d_in[6];
    const float* rph   = (const float*)d_in[7];
    const float* rpw   = (const float*)d_in[8];
    const float* n2g   = (const float*)d_in[9];
    const float* n2b   = (const float*)d_in[10];
    const float* l1w   = (const float*)d_in[11];
    const float* l1b   = (const float*)d_in[12];
    const float* l2w   = (const float*)d_in[13];
    const float* l2b   = (const float*)d_in[14];
    float* out = (float*)d_out;

    cudaFuncSetAttribute(attn_k, cudaFuncAttributeMaxDynamicSharedMemorySize, AT_SMEM);
    cudaFuncSetAttribute(tgemm_k<0>, cudaFuncAttributeMaxDynamicSharedMemorySize, SMEM_GEMM);
    cudaFuncSetAttribute(tgemm_k<1>, cudaFuncAttributeMaxDynamicSharedMemorySize, SMEM_GEMM);
    cudaFuncSetAttribute(tgemm_k<2>, cudaFuncAttributeMaxDynamicSharedMemorySize, SMEM_GEMM);
    cudaFuncSetAttribute(tgemm_k<3>, cudaFuncAttributeMaxDynamicSharedMemorySize, SMEM_GEMM);

    float *p_a1, *p_qkv, *p_at, *p_hid, *p_a2, *p_h;
    float *p_wq, *p_wp, *p_w1, *p_w2;
    cudaGetSymbolAddress((void**)&p_a1,  g_a1);
    cudaGetSymbolAddress((void**)&p_qkv, g_qkv);
    cudaGetSymbolAddress((void**)&p_at,  g_at);
    cudaGetSymbolAddress((void**)&p_hid, g_hid);
    cudaGetSymbolAddress((void**)&p_a2,  g_a2);
    cudaGetSymbolAddress((void**)&p_h,   g_h);
    cudaGetSymbolAddress((void**)&p_wq,  g_wq);
    cudaGetSymbolAddress((void**)&p_wp,  g_wp);
    cudaGetSymbolAddress((void**)&p_w1,  g_w1);
    cudaGetSymbolAddress((void**)&p_w2,  g_w2);

    dim3 tb(32, 8);
    wprep_k<<<dim3(3 * DIM / 32, DIM / 32), tb>>>(qkvw,  p_wq, DIM,  3 * DIM);
    wprep_k<<<dim3(DIM / 32, DIM / 32),     tb>>>(projw, p_wp, DIM,  DIM);

    // 1) LN1 + window-partition -> tf32 plane
    ln_k<<<MROWS, 192>>>(x, n1g, n1b, p_a1, 1);

    // 2) QKV GEMM -> fp32 qkv   (50176 x 2304 x 768)
    tgemm_k<0><<<dim3(18, 392), 128, SMEM_GEMM>>>(p_a1, p_wq,
        qkvb, nullptr, p_qkv, nullptr, MROWS, 3 * DIM, DIM);

    // 3) fused MMA attention -> tf32 plane
    attn_k<<<dim3(NWIN, NHD), 256, AT_SMEM>>>(p_qkv, rph, rpw, p_at);

    // 4) proj GEMM + unpartition + residual -> g_hid (fp32)
    tgemm_k<2><<<dim3(6, 392), 128, SMEM_GEMM>>>(p_at, p_wp,
        projb, x, p_hid, nullptr, MROWS, DIM, DIM);

    // 5) LN2 -> tf32 plane
    ln_k<<<MROWS, 192>>>(p_hid, n2g, n2b, p_a2, 0);

    wprep_k<<<dim3(MLPD / 32, DIM / 32), tb>>>(l1w, p_w1, DIM, MLPD);

    // 6) MLP1 + gelu -> tf32 plane   (50176 x 3072 x 768)
    tgemm_k<1><<<dim3(24, 392), 128, SMEM_GEMM>>>(p_a2, p_w1,
        l1b, nullptr, nullptr, p_h, MROWS, MLPD, DIM);

    wprep_k<<<dim3(DIM / 32, MLPD / 32), tb>>>(l2w, p_w2, MLPD, DIM);

    // 7) MLP2 + residual -> out (fp32)   (50176 x 768 x 3072)
    tgemm_k<3><<<dim3(6, 392), 128, SMEM_GEMM>>>(p_h, p_w2,
        l2b, p_hid, out, nullptr, MROWS, DIM, MLPD);
}

// round 14
// speedup vs baseline: 2.2878x; 1.0152x over previous
#include <cuda_runtime.h>
#include <math.h>
#include <stdint.h>

// ---------------- problem constants ----------------
#define BQ    16
#define ISZ   56
#define DIM   768
#define NHD   12
#define HDIM  64
#define WSZ   14
#define TOK   196
#define NWIN  256
#define MROWS 50176
#define MLPD  3072

typedef unsigned long long ull;

// ---------------- scratch (device globals) ----------------
__device__ __align__(16) float g_a1 [(size_t)MROWS * DIM];
__device__ __align__(16) float g_qkv[(size_t)MROWS * 3 * DIM];
__device__ __align__(16) float g_at [(size_t)MROWS * DIM];
__device__ __align__(16) float g_hid[(size_t)MROWS * DIM];
__device__ __align__(16) float g_a2 [(size_t)MROWS * DIM];
__device__ __align__(16) float g_h  [(size_t)MROWS * MLPD];
// transposed tf32-rounded weights: T[n][k]
__device__ __align__(16) float g_wq[(size_t)(3 * DIM) * DIM];
__device__ __align__(16) float g_wp[(size_t)DIM * DIM];
__device__ __align__(16) float g_w1[(size_t)MLPD * DIM];
__device__ __align__(16) float g_w2[(size_t)DIM * MLPD];

// ---------------- helpers ----------------
__device__ __forceinline__ float tf32r(float x) {
    uint32_t u;
    asm("cvt.rna.tf32.f32 %0, %1;" : "=r"(u) : "f"(x));
    return __uint_as_float(u);
}
__device__ __forceinline__ uint32_t smem_u32(const void* p) {
    uint32_t a;
    asm("{ .reg .u64 t; cvta.to.shared.u64 t, %1; cvt.u32.u64 %0, t; }" : "=r"(a) : "l"(p));
    return a;
}

// f32x2 packed math
__device__ __forceinline__ ull pk2(float lo, float hi) {
    ull r; asm("mov.b64 %0, {%1, %2};" : "=l"(r) : "f"(lo), "f"(hi)); return r;
}
__device__ __forceinline__ float2 upk2(ull v) {
    float2 f; asm("mov.b64 {%0, %1}, %2;" : "=f"(f.x), "=f"(f.y) : "l"(v)); return f;
}
__device__ __forceinline__ void fma2(ull& c, ull a, ull b) {
    asm("fma.rn.f32x2 %0, %1, %2, %3;" : "=l"(c) : "l"(a), "l"(b), "l"(c));
}

// window-token row m -> flat pixel p
__device__ __forceinline__ int m_to_p(int m) {
    int win = m / TOK, tok = m - win * TOK;
    int b = win >> 4, wr = win & 15;
    int wh = wr >> 2, ww = wr & 3;
    int i = tok / WSZ, j = tok - i * WSZ;
    return (b * ISZ + wh * WSZ + i) * ISZ + ww * WSZ + j;
}

__device__ __forceinline__ int div14(int x) { return (x * 37450) >> 19; }   // valid x < 256

// ---------------- mma / ldmatrix / cp.async (base sm_80+ PTX) --------------
__device__ __forceinline__ void mma1688t(float* d, const uint32_t* a, const uint32_t* b) {
    asm volatile("mma.sync.aligned.m16n8k8.row.col.f32.tf32.tf32.f32 "
        "{%0,%1,%2,%3},{%4,%5,%6,%7},{%8,%9},{%0,%1,%2,%3};"
        : "+f"(d[0]), "+f"(d[1]), "+f"(d[2]), "+f"(d[3])
        : "r"(a[0]), "r"(a[1]), "r"(a[2]), "r"(a[3]), "r"(b[0]), "r"(b[1]));
}
__device__ __forceinline__ void ldx4(uint32_t* r, uint32_t addr) {
    asm volatile("ldmatrix.sync.aligned.m8n8.x4.shared.b16 {%0,%1,%2,%3}, [%4];"
        : "=r"(r[0]), "=r"(r[1]), "=r"(r[2]), "=r"(r[3]) : "r"(addr));
}
__device__ __forceinline__ void cpa16(uint32_t dst, const void* src) {
    asm volatile("cp.async.cg.shared.global [%0], [%1], 16;" :: "r"(dst), "l"(src));
}
#define CP_COMMIT() asm volatile("cp.async.commit_group;" ::: "memory")
#define CP_WAIT1()  asm volatile("cp.async.wait_group 1;" ::: "memory")

// ---------------- weight transpose -> tf32-rounded fp32 ----------------
__global__ void __launch_bounds__(256) wprep_k(const float* __restrict__ W,
                                               float* __restrict__ T,
                                               int K, int N) {
    __shared__ float t[32][33];
    int nb = blockIdx.x * 32, kb = blockIdx.y * 32;
    int tx = threadIdx.x, ty = threadIdx.y;
#pragma unroll
    for (int j = 0; j < 32; j += 8)
        t[ty + j][tx] = W[(size_t)(kb + ty + j) * N + nb + tx];
    __syncthreads();
#pragma unroll
    for (int j = 0; j < 32; j += 8)
        T[(size_t)(nb + ty + j) * K + kb + tx] = tf32r(t[tx][ty + j]);
}

// ---------------- LayerNorm: warp-per-row, no smem -------------------------
__global__ void __launch_bounds__(256) ln_k(const float* __restrict__ in,
                                            const float* __restrict__ gg,
                                            const float* __restrict__ bb,
                                            float* __restrict__ o,
                                            int windowed) {
    int row = blockIdx.x * 8 + (threadIdx.x >> 5);
    int lane = threadIdx.x & 31;
    int src = windowed ? m_to_p(row) : row;
    const float* xr = in + (size_t)src * DIM;
    float4 v[6];
    float s = 0.f, sq = 0.f;
#pragma unroll
    for (int j = 0; j < 6; j++) {
        v[j] = *(const float4*)(xr + 4 * (lane + 32 * j));
        s  += v[j].x + v[j].y + v[j].z + v[j].w;
        sq += v[j].x * v[j].x + v[j].y * v[j].y + v[j].z * v[j].z + v[j].w * v[j].w;
    }
#pragma unroll
    for (int off = 16; off > 0; off >>= 1) {
        s  += __shfl_xor_sync(0xffffffffu, s, off);
        sq += __shfl_xor_sync(0xffffffffu, sq, off);
    }
    float mu = s * (1.0f / 768.0f);
    float var = sq * (1.0f / 768.0f) - mu * mu;
    float rstd = rsqrtf(var + 1e-5f);
    float* orow = o + (size_t)row * DIM;
#pragma unroll
    for (int j = 0; j < 6; j++) {
        int c = 4 * (lane + 32 * j);
        float4 g = *(const float4*)(gg + c);
        float4 b = *(const float4*)(bb + c);
        float4 w;
        w.x = tf32r((v[j].x - mu) * rstd * g.x + b.x);
        w.y = tf32r((v[j].y - mu) * rstd * g.y + b.y);
        w.z = tf32r((v[j].z - mu) * rstd * g.z + b.z);
        w.w = tf32r((v[j].w - mu) * rstd * g.w + b.w);
        *(float4*)(orow + c) = w;
    }
}

// ---------------- tf32 HMMA GEMM: hoisted B-fragments ----------------------
// CTA 128x128, 4 warps of 64x64, k-chunk 32, 3-stage cp.async, 2 CTAs/SM.
// All 8 B-fragments per k16 step loaded before the 64-mma stream.
#define ROWB 144
#define A_PL (128 * ROWB)
#define STAGE_BYTES (2 * A_PL)
#define SMEM_GEMM (3 * STAGE_BYTES + 256)

template <int EPI>
__global__ void __launch_bounds__(128, 2)
tgemm_k(const float* __restrict__ A, const float* __restrict__ B,
        const float* __restrict__ bias, const float* __restrict__ res,
        float* __restrict__ C, float* __restrict__ Cr,
        int M, int N, int K) {
    extern __shared__ char dyn[];
    uint32_t sb = (smem_u32(dyn) + 255) & ~255u;

    const int tid = threadIdx.x, lane = tid & 31, wid = tid >> 5;
    const int bm = blockIdx.y * 128, bn = blockIdx.x * 128;
    const int wm = (wid >> 1) * 64, wn = (wid & 1) * 64;
    const int nk = K >> 5;

    const float* gp[16]; uint32_t so[16];
#pragma unroll
    for (int q = 0; q < 16; q++) {
        int i = tid + q * 128;
        int isB = i >> 10, j = i & 1023, r = j >> 3, c = j & 7;
        gp[q] = (isB ? B + (size_t)(bn + r) * K : A + (size_t)(bm + r) * K) + c * 4;
        so[q] = (uint32_t)(isB * A_PL + r * ROWB + c * 16);
    }

    auto issue = [&](int stage, int t) {
        uint32_t s = sb + stage * STAGE_BYTES;
        int k0 = t * 32;
#pragma unroll
        for (int q = 0; q < 16; q++) cpa16(s + so[q], gp[q] + k0);
    };

    float acc[128];
#pragma unroll
    for (int i = 0; i < 128; i++) acc[i] = 0.f;

    const uint32_t aoff = (uint32_t)((((lane & 7) + ((lane >> 3) & 1) * 8) * ROWB) + (lane >> 4) * 16);
    const uint32_t boff = (uint32_t)((lane & 7) * ROWB + (lane >> 3) * 16);

    issue(0, 0); CP_COMMIT();
    issue(1, 1); CP_COMMIT();

    for (int t = 0; t < nk; ++t) {
        CP_WAIT1();
        __syncthreads();
        if (t + 2 < nk) issue((t + 2) % 3, t + 2);
        CP_COMMIT();

        uint32_t s = sb + (t % 3) * STAGE_BYTES;
#pragma unroll
        for (int sp = 0; sp < 2; sp++) {
            // hoist ALL fragments for this k16 step: 8 A-ldx4 + 8 B-ldx4,
            // then a pure 64-mma stream (no interleaved shared loads).
            uint32_t af[2][4][4];
            uint32_t bfr[8][4];
#pragma unroll
            for (int ks = 0; ks < 2; ks++)
#pragma unroll
                for (int mi = 0; mi < 4; mi++)
                    ldx4(af[ks][mi], s + (uint32_t)((wm + mi * 16) * ROWB) + (sp * 2 + ks) * 32 + aoff);
#pragma unroll
            for (int p = 0; p < 8; p++)
                ldx4(bfr[p], s + A_PL + (uint32_t)((wn + p * 8) * ROWB) + sp * 64 + boff);
#pragma unroll
            for (int p = 0; p < 8; p++) {
#pragma unroll
                for (int mi = 0; mi < 4; mi++)
                    mma1688t(&acc[(mi * 8 + p) * 4], af[0][mi], bfr[p]);
#pragma unroll
                for (int mi = 0; mi < 4; mi++)
                    mma1688t(&acc[(mi * 8 + p) * 4], af[1][mi], bfr[p] + 2);
            }
        }
    }

#pragma unroll
    for (int mi = 0; mi < 4; mi++) {
        int r0 = bm + wm + mi * 16 + (lane >> 2);
#pragma unroll
        for (int p = 0; p < 8; p++) {
            int gn = bn + wn + p * 8 + (lane & 3) * 2;
            float* a = &acc[(mi * 8 + p) * 4];
            float b0 = bias[gn], b1 = bias[gn + 1];
#pragma unroll
            for (int h = 0; h < 2; h++) {
                int row = r0 + h * 8;
                float x0 = a[h * 2] + b0, x1 = a[h * 2 + 1] + b1;
                if (EPI == 1) {
                    float g0 = 0.5f * x0 * (1.0f + erff(x0 * 0.70710678118654752f));
                    float g1 = 0.5f * x1 * (1.0f + erff(x1 * 0.70710678118654752f));
                    float2 o; o.x = tf32r(g0); o.y = tf32r(g1);
                    *(float2*)(Cr + (size_t)row * N + gn) = o;
                } else if (EPI == 2) {
                    int pp = m_to_p(row);
                    const float* rp = res + (size_t)pp * DIM + gn;
                    float2 o; o.x = x0 + rp[0]; o.y = x1 + rp[1];
                    *(float2*)(C + (size_t)pp * DIM + gn) = o;
                } else if (EPI == 3) {
                    const float* rp = res + (size_t)row * N + gn;
                    float2 o; o.x = x0 + rp[0]; o.y = x1 + rp[1];
                    *(float2*)(C + (size_t)row * N + gn) = o;
                } else {
                    float2 o; o.x = x0; o.y = x1;
                    *(float2*)(C + (size_t)row * N + gn) = o;
                }
            }
        }
    }
}

// ---------------- fused tf32-MMA window attention (256 threads) ------------
#define AT_KROW 272
#define AT_VROW 848
#define AT_SM_K  0
#define AT_SM_V  (200 * AT_KROW)                   // 54400
#define AT_SM_T1 (AT_SM_V + 64 * AT_VROW)          // 108672
#define AT_SM_T2 (AT_SM_T1 + 208 * 28 * 4)         // 131968
#define AT_SM_Q  (AT_SM_T2 + 208 * 28 * 4)         // 155264
#define AT_SMEM  (AT_SM_Q + 8 * 16 * AT_KROW)      // 190080

// build m16k8 A-fragment of P from S-acc layout via quad shuffles
__device__ __forceinline__ void pfrag(const float* s4, uint32_t* a, int lane) {
    int j0 = lane & 3;
    int sA = (lane & ~3) | (j0 >> 1);
    float c0lo = __shfl_sync(0xffffffffu, s4[0], sA);
    float c1lo = __shfl_sync(0xffffffffu, s4[1], sA);
    float c2lo = __shfl_sync(0xffffffffu, s4[2], sA);
    float c3lo = __shfl_sync(0xffffffffu, s4[3], sA);
    float c0hi = __shfl_sync(0xffffffffu, s4[0], sA + 2);
    float c1hi = __shfl_sync(0xffffffffu, s4[1], sA + 2);
    float c2hi = __shfl_sync(0xffffffffu, s4[2], sA + 2);
    float c3hi = __shfl_sync(0xffffffffu, s4[3], sA + 2);
    bool odd = (j0 & 1) != 0;
    a[0] = __float_as_uint(odd ? c1lo : c0lo);
    a[1] = __float_as_uint(odd ? c3lo : c2lo);
    a[2] = __float_as_uint(odd ? c1hi : c0hi);
    a[3] = __float_as_uint(odd ? c3hi : c2hi);
}

__global__ void __launch_bounds__(256) attn_k(const float* __restrict__ qkv,
                                              const float* __restrict__ rph,
                                              const float* __restrict__ rpw,
                                              float* __restrict__ o) {
    extern __shared__ char sm[];
    uint32_t sb = smem_u32(sm);
    const int win = blockIdx.x, head = blockIdx.y;
    const int tid = threadIdx.x, lane = tid & 31, wid = tid >> 5;
    const float* base = qkv + (size_t)win * TOK * (3 * DIM) + head * HDIM;

    // ---- K (keys 0..199; pad rows zero), tf32-rounded ----
    for (int i = tid; i < 200 * 16; i += 256) {
        int r = i >> 4, c4 = (i & 15) << 2;
        float4 v = make_float4(0.f, 0.f, 0.f, 0.f);
        if (r < TOK) v = *(const float4*)(base + (size_t)r * (3 * DIM) + DIM + c4);
        float4 w; w.x = tf32r(v.x); w.y = tf32r(v.y); w.z = tf32r(v.z); w.w = tf32r(v.w);
        *(float4*)(sm + AT_SM_K + r * AT_KROW + c4 * 4) = w;
    }
    // ---- V transposed: V^T[dim][key] ----
    for (int r = tid; r < TOK; r += 256) {
        const float* src = base + (size_t)r * (3 * DIM) + 2 * DIM;
#pragma unroll
        for (int d4 = 0; d4 < HDIM; d4 += 4) {
            float4 v = *(const float4*)(src + d4);
            *(float*)(sm + AT_SM_V + (d4 + 0) * AT_VROW + r * 4) = tf32r(v.x);
            *(float*)(sm + AT_SM_V + (d4 + 1) * AT_VROW + r * 4) = tf32r(v.y);
            *(float*)(sm + AT_SM_V + (d4 + 2) * AT_VROW + r * 4) = tf32r(v.z);
            *(float*)(sm + AT_SM_V + (d4 + 3) * AT_VROW + r * 4) = tf32r(v.w);
        }
    }
    // zero V^T pad keys 196..199
    for (int i = tid; i < 64 * 4; i += 256) {
        int r = i >> 2, c = 196 + (i & 3);
        *(float*)(sm + AT_SM_V + r * AT_VROW + c * 4) = 0.f;
    }
    // ---- bias tables T1[q][idx] = q . rph[idx], T2 likewise ----
    for (int q = tid; q < 208; q += 256) {
        float* t1 = (float*)(sm + AT_SM_T1) + q * 28;
        float* t2 = (float*)(sm + AT_SM_T2) + q * 28;
        if (q < TOK) {
            ull qr[32];
#pragma unroll
            for (int d = 0; d < HDIM; d += 4) {
                float4 v = *(const float4*)(base + (size_t)q * (3 * DIM) + d);
                qr[d >> 1]       = pk2(v.x, v.y);
                qr[(d >> 1) + 1] = pk2(v.z, v.w);
            }
            for (int idx = 0; idx < 27; idx++) {
                const ull* r1 = (const ull*)(rph + (size_t)idx * HDIM);
                const ull* r2 = (const ull*)(rpw + (size_t)idx * HDIM);
                ull a0 = 0, a1 = 0, b0 = 0, b1 = 0;
#pragma unroll
                for (int j = 0; j < 32; j += 2) {
                    fma2(a0, qr[j], r1[j]); fma2(a1, qr[j + 1], r1[j + 1]);
                    fma2(b0, qr[j], r2[j]); fma2(b1, qr[j + 1], r2[j + 1]);
                }
                float2 fa0 = upk2(a0), fa1 = upk2(a1), fb0 = upk2(b0), fb1 = upk2(b1);
                t1[idx] = fa0.x + fa0.y + fa1.x + fa1.y;
                t2[idx] = fb0.x + fb0.y + fb1.x + fb1.y;
            }
        } else {
            for (int idx = 0; idx < 28; idx++) { t1[idx] = 0.f; t2[idx] = 0.f; }
        }
    }
    __syncthreads();

    const uint32_t aoff  = (uint32_t)((((lane & 7) + ((lane >> 3) & 1) * 8) * AT_KROW) + (lane >> 4) * 16);
    const uint32_t boffK = (uint32_t)((lane & 7) * AT_KROW + (lane >> 3) * 16);
    const uint32_t boffV = (uint32_t)((lane & 7) * AT_VROW + (lane >> 3) * 16);
    const uint32_t qstage = sb + AT_SM_Q + wid * 16 * AT_KROW;

    for (int mt = wid; mt < 13; mt += 8) {
        const int mrow0 = mt * 16;
        // stage Q tile (scaled, tf32-rounded; clamp pad rows)
        for (int i = lane; i < 16 * 16; i += 32) {
            int r = i >> 4, c4 = (i & 15) << 2;
            int gr = mrow0 + r; if (gr > TOK - 1) gr = TOK - 1;
            float4 v = *(const float4*)(base + (size_t)gr * (3 * DIM) + c4);
            float4 w; w.x = tf32r(v.x * 0.125f); w.y = tf32r(v.y * 0.125f);
            w.z = tf32r(v.z * 0.125f); w.w = tf32r(v.w * 0.125f);
            *(float4*)(sm + AT_SM_Q + wid * 16 * AT_KROW + r * AT_KROW + c4 * 4) = w;
        }
        __syncwarp();
        uint32_t qf[8][4];
#pragma unroll
        for (int ks = 0; ks < 8; ks++) ldx4(qf[ks], qstage + ks * 32 + aoff);

        // ---- S = Qs @ K^T (25 n-tiles); j covers dims 16j..16j+15 -> j*64 B ----
        float sc[25][4];
#pragma unroll
        for (int nt = 0; nt < 25; nt++) { sc[nt][0] = 0.f; sc[nt][1] = 0.f; sc[nt][2] = 0.f; sc[nt][3] = 0.f; }
#pragma unroll
        for (int j = 0; j < 4; j++) {
#pragma unroll
            for (int nt = 0; nt < 25; nt++) {
                uint32_t bf[4];
                ldx4(bf, sb + AT_SM_K + (uint32_t)(nt * 8 * AT_KROW) + j * 64 + boffK);
                mma1688t(sc[nt], qf[2 * j], bf);
                mma1688t(sc[nt], qf[2 * j + 1], bf + 2);
            }
        }

        // ---- bias + mask + softmax (exact, full row in regs) ----
        const int rA = mrow0 + (lane >> 2), rB = rA + 8;
        const int qiA = div14(rA), qjA = rA - qiA * 14;
        const int qiB = div14(rB), qjB = rB - qiB * 14;
        const float* T1A = (const float*)(sm + AT_SM_T1) + rA * 28 + qiA + 13;
        const float* T2A = (const float*)(sm + AT_SM_T2) + rA * 28 + qjA + 13;
        const float* T1B = (const float*)(sm + AT_SM_T1) + rB * 28 + qiB + 13;
        const float* T2B = (const float*)(sm + AT_SM_T2) + rB * 28 + qjB + 13;
        float mxA = -3e38f, mxB = -3e38f;
#pragma unroll
        for (int nt = 0; nt < 25; nt++) {
            int c0 = nt * 8 + 2 * (lane & 3), c1 = c0 + 1;
            int cc0 = c0 > 195 ? 195 : c0, cc1 = c1 > 195 ? 195 : c1;
            int kh0 = div14(cc0), kw0 = cc0 - kh0 * 14;
            int kh1 = div14(cc1), kw1 = cc1 - kh1 * 14;
            sc[nt][0] = (c0 < TOK) ? sc[nt][0] + T1A[-kh0] + T2A[-kw0] : -3e38f;
            sc[nt][1] = (c1 < TOK) ? sc[nt][1] + T1A[-kh1] + T2A[-kw1] : -3e38f;
            sc[nt][2] = (c0 < TOK) ? sc[nt][2] + T1B[-kh0] + T2B[-kw0] : -3e38f;
            sc[nt][3] = (c1 < TOK) ? sc[nt][3] + T1B[-kh1] + T2B[-kw1] : -3e38f;
            mxA = fmaxf(mxA, fmaxf(sc[nt][0], sc[nt][1]));
            mxB = fmaxf(mxB, fmaxf(sc[nt][2], sc[nt][3]));
        }
        mxA = fmaxf(mxA, __shfl_xor_sync(0xffffffffu, mxA, 1));
        mxA = fmaxf(mxA, __shfl_xor_sync(0xffffffffu, mxA, 2));
        mxB = fmaxf(mxB, __shfl_xor_sync(0xffffffffu, mxB, 1));
        mxB = fmaxf(mxB, __shfl_xor_sync(0xffffffffu, mxB, 2));
        float lA = 0.f, lB = 0.f;
#pragma unroll
        for (int nt = 0; nt < 25; nt++) {
            float p0 = __expf(sc[nt][0] - mxA);
            float p1 = __expf(sc[nt][1] - mxA);
            float p2 = __expf(sc[nt][2] - mxB);
            float p3 = __expf(sc[nt][3] - mxB);
            lA += p0 + p1; lB += p2 + p3;
            sc[nt][0] = tf32r(p0); sc[nt][1] = tf32r(p1);
            sc[nt][2] = tf32r(p2); sc[nt][3] = tf32r(p3);
        }
        lA += __shfl_xor_sync(0xffffffffu, lA, 1);
        lA += __shfl_xor_sync(0xffffffffu, lA, 2);
        lB += __shfl_xor_sync(0xffffffffu, lB, 1);
        lB += __shfl_xor_sync(0xffffffffu, lB, 2);

        // ---- O = P @ V (8 dim-tiles) ----
        float oa[8][4];
#pragma unroll
        for (int nt8 = 0; nt8 < 8; nt8++) { oa[nt8][0] = 0.f; oa[nt8][1] = 0.f; oa[nt8][2] = 0.f; oa[nt8][3] = 0.f; }
#pragma unroll
        for (int cp = 0; cp < 12; cp++) {
            uint32_t pa0[4], pa1[4];
            pfrag(sc[2 * cp], pa0, lane);
            pfrag(sc[2 * cp + 1], pa1, lane);
#pragma unroll
            for (int nt8 = 0; nt8 < 8; nt8++) {
                uint32_t bf[4];
                ldx4(bf, sb + AT_SM_V + (uint32_t)(nt8 * 8 * AT_VROW) + cp * 64 + boffV);
                mma1688t(oa[nt8], pa0, bf);
                mma1688t(oa[nt8], pa1, bf + 2);
            }
        }
        {   // tail chunk 24 (keys 192..199)
            uint32_t pa[4];
            pfrag(sc[24], pa, lane);
#pragma unroll
            for (int nt8 = 0; nt8 < 8; nt8++) {
                uint32_t bf[4];
                ldx4(bf, sb + AT_SM_V + (uint32_t)(nt8 * 8 * AT_VROW) + 12 * 64 + boffV);
                mma1688t(oa[nt8], pa, bf);
            }
        }

        // ---- normalize + store ----
        float invA = 1.f / lA, invB = 1.f / lB;
        if (rA < TOK) {
            float* dst = o + ((size_t)(win * TOK + rA)) * DIM + head * HDIM;
#pragma unroll
            for (int nt8 = 0; nt8 < 8; nt8++) {
                int n = nt8 * 8 + 2 * (lane & 3);
                float2 w; w.x = tf32r(oa[nt8][0] * invA); w.y = tf32r(oa[nt8][1] * invA);
                *(float2*)(dst + n) = w;
            }
        }
        if (rB < TOK) {
            float* dst = o + ((size_t)(win * TOK + rB)) * DIM + head * HDIM;
#pragma unroll
            for (int nt8 = 0; nt8 < 8; nt8++) {
                int n = nt8 * 8 + 2 * (lane & 3);
                float2 w; w.x = tf32r(oa[nt8][2] * invB); w.y = tf32r(oa[nt8][3] * invB);
                *(float2*)(dst + n) = w;
            }
        }
    }
}

// ---------------- launcher ----------------
extern "C" void kernel_launch(void* const* d_in, const int* in_sizes, int n_in,
                              void* d_out, int out_size) {
    const float* x     = (const float*)d_in[0];
    const float* n1g   = (const float*)d_in[1];
    const float* n1b   = (const float*)d_in[2];
    const float* qkvw  = (const float*)d_in[3];
    const float* qkvb  = (const float*)d_in[4];
    const float* projw = (const float*)d_in[5];
    const float* projb = (const float*)d_in[6];
    const float* rph   = (const float*)d_in[7];
    const float* rpw   = (const float*)d_in[8];
    const float* n2g   = (const float*)d_in[9];
    const float* n2b   = (const float*)d_in[10];
    const float* l1w   = (const float*)d_in[11];
    const float* l1b   = (const float*)d_in[12];
    const float* l2w   = (const float*)d_in[13];
    const float* l2b   = (const float*)d_in[14];
    float* out = (float*)d_out;

    cudaFuncSetAttribute(attn_k, cudaFuncAttributeMaxDynamicSharedMemorySize, AT_SMEM);
    cudaFuncSetAttribute(tgemm_k<0>, cudaFuncAttributeMaxDynamicSharedMemorySize, SMEM_GEMM);
    cudaFuncSetAttribute(tgemm_k<1>, cudaFuncAttributeMaxDynamicSharedMemorySize, SMEM_GEMM);
    cudaFuncSetAttribute(tgemm_k<2>, cudaFuncAttributeMaxDynamicSharedMemorySize, SMEM_GEMM);
    cudaFuncSetAttribute(tgemm_k<3>, cudaFuncAttributeMaxDynamicSharedMemorySize, SMEM_GEMM);

    float *p_a1, *p_qkv, *p_at, *p_hid, *p_a2, *p_h;
    float *p_wq, *p_wp, *p_w1, *p_w2;
    cudaGetSymbolAddress((void**)&p_a1,  g_a1);
    cudaGetSymbolAddress((void**)&p_qkv, g_qkv);
    cudaGetSymbolAddress((void**)&p_at,  g_at);
    cudaGetSymbolAddress((void**)&p_hid, g_hid);
    cudaGetSymbolAddress((void**)&p_a2,  g_a2);
    cudaGetSymbolAddress((void**)&p_h,   g_h);
    cudaGetSymbolAddress((void**)&p_wq,  g_wq);
    cudaGetSymbolAddress((void**)&p_wp,  g_wp);
    cudaGetSymbolAddress((void**)&p_w1,  g_w1);
    cudaGetSymbolAddress((void**)&p_w2,  g_w2);

    dim3 tb(32, 8);
    wprep_k<<<dim3(3 * DIM / 32, DIM / 32), tb>>>(qkvw,  p_wq, DIM,  3 * DIM);
    wprep_k<<<dim3(DIM / 32, DIM / 32),     tb>>>(projw, p_wp, DIM,  DIM);

    // 1) LN1 + window-partition -> tf32 plane (warp-per-row)
    ln_k<<<MROWS / 8, 256>>>(x, n1g, n1b, p_a1, 1);

    // 2) QKV GEMM -> fp32 qkv   (50176 x 2304 x 768)
    tgemm_k<0><<<dim3(18, 392), 128, SMEM_GEMM>>>(p_a1, p_wq,
        qkvb, nullptr, p_qkv, nullptr, MROWS, 3 * DIM, DIM);

    // 3) fused MMA attention -> tf32 plane
    attn_k<<<dim3(NWIN, NHD), 256, AT_SMEM>>>(p_qkv, rph, rpw, p_at);

    // 4) proj GEMM + unpartition + residual -> g_hid (fp32)
    tgemm_k<2><<<dim3(6, 392), 128, SMEM_GEMM>>>(p_at, p_wp,
        projb, x, p_hid, nullptr, MROWS, DIM, DIM);

    // 5) LN2 -> tf32 plane
    ln_k<<<MROWS / 8, 256>>>(p_hid, n2g, n2b, p_a2, 0);

    wprep_k<<<dim3(MLPD / 32, DIM / 32), tb>>>(l1w, p_w1, DIM, MLPD);

    // 6) MLP1 + gelu -> tf32 plane   (50176 x 3072 x 768)
    tgemm_k<1><<<dim3(24, 392), 128, SMEM_GEMM>>>(p_a2, p_w1,
        l1b, nullptr, nullptr, p_h, MROWS, MLPD, DIM);

    wprep_k<<<dim3(DIM / 32, MLPD / 32), tb>>>(l2w, p_w2, MLPD, DIM);

    // 7) MLP2 + residual -> out (fp32)   (50176 x 768 x 3072)
    tgemm_k<3><<<dim3(6, 392), 128, SMEM_GEMM>>>(p_h, p_w2,
        l2b, p_hid, out, nullptr, MROWS, DIM, MLPD);
}